// round 7
// baseline (speedup 1.0000x reference)
#include <cuda_runtime.h>
#include <math.h>

#define C_    256
#define T_    8
#define H_    32
#define W_    32
#define L_    4
#define THW_  8192
#define NROWS 256              // L * 64 sample points
#define FEAT_OUT_ELEMS (C_*THW_*L_)   // 2097152
#define KC 128

// ---- scratch (device globals; no allocation) ----
__device__ float g_glob[L_*C_];           // glob[l][c]
__device__ float g_X [NROWS*768];         // MLP input rows
__device__ float g_H1[NROWS*256];
__device__ float g_H2[NROWS*256];
__device__ int   g_uq[NROWS*40];          // dedup indices (compact)
__device__ float g_uw[NROWS*40];          // dedup weights (compact)
__device__ int   g_nq[NROWS];             // dedup counts

__constant__ int c_tt[4] = {1,3,4,6};
__constant__ int c_hh[4] = {4,12,19,27};

__device__ __forceinline__ int flat_idx(int n){
    int it = n >> 4, ih = (n >> 2) & 3, iw = n & 3;
    return (c_tt[it]*H_ + c_hh[ih])*W_ + c_hh[iw];
}
__device__ __forceinline__ float sigmoidf_(float x){ return 1.0f/(1.0f+expf(-x)); }
__device__ __forceinline__ float invsigf_(float x){
    return logf(fmaxf(x,1e-5f)/fmaxf(1.0f-x,1e-5f));
}
__device__ __forceinline__ void cp_async16(void* smem_dst, const void* gmem_src){
    unsigned s = (unsigned)__cvta_generic_to_shared(smem_dst);
    asm volatile("cp.async.cg.shared.global [%0], [%1], 16;\n" :: "r"(s), "l"(gmem_src));
}
__device__ __forceinline__ void cp_commit(){ asm volatile("cp.async.commit_group;\n"); }
__device__ __forceinline__ void cp_wait0(){ asm volatile("cp.async.wait_group 0;\n"); }
__device__ __forceinline__ void cp_wait1(){ asm volatile("cp.async.wait_group 1;\n"); }

typedef unsigned long long ull;
__device__ __forceinline__ ull fma2_(ull a, ull b, ull c){
    ull d; asm("fma.rn.f32x2 %0, %1, %2, %3;" : "=l"(d) : "l"(a), "l"(b), "l"(c)); return d;
}
__device__ __forceinline__ ull pack2_(float x, float y){
    ull r; asm("mov.b64 %0, {%1, %2};" : "=l"(r) : "f"(x), "f"(y)); return r;
}
__device__ __forceinline__ float2 unpack2_(ull v){
    float2 r; asm("mov.b64 {%0, %1}, %2;" : "=f"(r.x), "=f"(r.y) : "l"(v)); return r;
}

// ============================================================
// Kernel 1: glob (channel mean) + beta fill, one block per channel
// ============================================================
__global__ void glob_fill_kernel(const float* __restrict__ feats,
                                 const float* __restrict__ beta,
                                 float4* __restrict__ out4){
    int c = blockIdx.x;
    int t = threadIdx.x;
    const float4* f4 = reinterpret_cast<const float4*>(feats + (size_t)c * (THW_*L_));
    float4 s = make_float4(0.f,0.f,0.f,0.f);
    for (int i = t; i < THW_; i += 256){
        float4 v = f4[i];
        s.x += v.x; s.y += v.y; s.z += v.z; s.w += v.w;
    }
    // beta fill of this channel's whole region (sample overwrites its spots later)
    float b = __ldg(&beta[c]);
    float4 bv = make_float4(b,b,b,b);
    float4* ob = out4 + (size_t)c * THW_;
    for (int i = t; i < THW_; i += 256) ob[i] = bv;

    __shared__ float4 sm[256];
    sm[t] = s;
    __syncthreads();
    for (int o = 128; o > 0; o >>= 1){
        if (t < o){
            float4 a = sm[t], bb = sm[t+o];
            sm[t] = make_float4(a.x+bb.x, a.y+bb.y, a.z+bb.z, a.w+bb.w);
        }
        __syncthreads();
    }
    if (t == 0){
        float4 v = sm[0];
        const float inv = 1.0f/8192.0f;
        g_glob[0*C_+c] = v.x*inv;
        g_glob[1*C_+c] = v.y*inv;
        g_glob[2*C_+c] = v.z*inv;
        g_glob[3*C_+c] = v.w*inv;
    }
}

// ============================================================
// Kernel 2: materialize X[256][768] = [feat | pos | glob]
// ============================================================
__global__ void xprep_kernel(const float* __restrict__ feats, const float* __restrict__ pos){
    int rr = blockIdx.x;
    int l  = rr >> 6;
    int p  = flat_idx(rr & 63);
    for (int k = threadIdx.x; k < 768; k += 256){
        float v;
        if (k < 256)       v = feats[((size_t)k*THW_ + p)*L_ + l];
        else if (k < 512)  v = pos  [((size_t)(k-256)*THW_ + p)*L_ + l];
        else               v = g_glob[l*C_ + (k-512)];
        g_X[rr*768 + k] = v;
    }
}

// ============================================================
// Tiled GEMM + relu: O[256,256] = relu(Xg[256,KDIM] @ Wg[KDIM,256] + bias)
// grid (8 col-tiles, 16 row-tiles), 256 threads.
// Tile: 16 rows x 32 cols; thread = (j = t&31, rp = t>>5) -> rows 2rp,2rp+1.
// smem: Xs[KDIM*18] (k-major, 16 rows padded to 18) + Wb[2][KC*32]
// ============================================================
template<int KDIM>
__device__ __forceinline__ void gemm_tile(const float* __restrict__ Xg,
                                          const float* __restrict__ Wg,
                                          const float* __restrict__ bias,
                                          float* __restrict__ Og){
    extern __shared__ float sm[];
    float* Xs  = sm;
    float* Wb0 = sm + KDIM*18;
    float* Wb1 = Wb0 + KC*32;

    int t  = threadIdx.x;
    int c0 = blockIdx.x * 32;
    int r0 = blockIdx.y * 16;
    constexpr int NCH = KDIM / KC;

    // prefetch W chunk 0
    {
        #pragma unroll
        for (int u = 0; u < 4; u++){
            int idx4 = t + u*256;                  // 1024 float4 = 128x32
            int kk = idx4 >> 3, j2 = (idx4 & 7)*4;
            cp_async16(Wb0 + idx4*4, Wg + (size_t)kk*256 + c0 + j2);
        }
        cp_commit();
    }

    // load Xs[k*18 + row] from Xg row-major (coalesced float4 reads)
    {
        const float4* X4 = reinterpret_cast<const float4*>(Xg);
        constexpr int K4 = KDIM/4;
        for (int idx4 = t; idx4 < 16*K4; idx4 += 256){
            int row = idx4 / K4;
            int k4  = idx4 - row*K4;
            float4 v = X4[(size_t)(r0+row)*K4 + k4];
            int k = k4*4;
            Xs[(k+0)*18 + row] = v.x;
            Xs[(k+1)*18 + row] = v.y;
            Xs[(k+2)*18 + row] = v.z;
            Xs[(k+3)*18 + row] = v.w;
        }
    }

    int j = t & 31, rp = t >> 5;
    ull accA = 0ULL, accB = 0ULL;

    #pragma unroll 1
    for (int ch = 0; ch < NCH; ch++){
        float* Wcur = (ch & 1) ? Wb1 : Wb0;
        float* Wnxt = (ch & 1) ? Wb0 : Wb1;
        if (ch + 1 < NCH){
            #pragma unroll
            for (int u = 0; u < 4; u++){
                int idx4 = t + u*256;
                int kk = idx4 >> 3, j2 = (idx4 & 7)*4;
                cp_async16(Wnxt + idx4*4, Wg + (size_t)((ch+1)*KC + kk)*256 + c0 + j2);
            }
            cp_commit();
            cp_wait1();
        } else {
            cp_wait0();
        }
        __syncthreads();
        const float* Xb = Xs + ch*KC*18 + 2*rp;
        #pragma unroll 8
        for (int kk = 0; kk < KC; kk += 2){
            float wA = Wcur[kk*32 + j];
            ull xA = *(const ull*)(Xb + kk*18);
            accA = fma2_(xA, pack2_(wA, wA), accA);
            float wB = Wcur[(kk+1)*32 + j];
            ull xB = *(const ull*)(Xb + (kk+1)*18);
            accB = fma2_(xB, pack2_(wB, wB), accB);
        }
        __syncthreads();
    }

    float2 a = unpack2_(accA), b2v = unpack2_(accB);
    float bb = __ldg(&bias[c0 + j]);
    int row = r0 + 2*rp;
    Og[(size_t)row*256 + c0 + j]     = fmaxf(a.x + b2v.x + bb, 0.f);
    Og[(size_t)(row+1)*256 + c0 + j] = fmaxf(a.y + b2v.y + bb, 0.f);
}

__global__ void __launch_bounds__(256, 2)
mlp1_kernel(const float* __restrict__ W1, const float* __restrict__ b1){
    gemm_tile<768>(g_X, W1, b1, g_H1);
}
__global__ void __launch_bounds__(256, 2)
mlp2_kernel(const float* __restrict__ W2, const float* __restrict__ b2){
    gemm_tile<256>(g_H1, W2, b2, g_H2);
}

// ============================================================
// Kernel 5: heads + dedup tables. 256 blocks (one row) x 128 threads.
// (wl head removed: softmax row-sum == 1 and LN is scale-invariant)
// ============================================================
__global__ void heads_kernel(
    const float* __restrict__ Wn, const float* __restrict__ bn,
    const float* __restrict__ Woff, const float* __restrict__ boff,
    const float* __restrict__ Ww, const float* __restrict__ bw,
    float* __restrict__ out, int write_next)
{
    __shared__ float Hs[256];
    __shared__ float HWn[768], HWo[192], HWw[128];
    __shared__ float HD[28];
    __shared__ float SPx[4], SPy[4], SPz[4], SPw[4];
    __shared__ int   cq[40];
    __shared__ float cw[40];
    __shared__ int   s_nq;

    int rr = blockIdx.x;
    int t  = threadIdx.x;
    int p  = flat_idx(rr & 63);

    Hs[t] = g_H2[rr*256 + t];
    Hs[t+128] = g_H2[rr*256 + t + 128];
    for (int k = t; k < 768; k += 128) HWn[k] = Wn[k];
    for (int k = t; k < 192; k += 128) HWo[k] = Woff[k];
    HWw[t] = Ww[t];
    __syncthreads();

    if (t < 3){                               // nxt
        float s = bn[t];
        #pragma unroll 8
        for (int k = 0; k < 256; k++) s = fmaf(Hs[k], HWn[k*3 + t], s);
        HD[t] = s;
    } else if (t >= 8 && t < 20){             // offsets
        int u = t - 8;
        int no = u / 3, jo = u - no*3;
        float s = boff[jo];
        #pragma unroll 8
        for (int dd = 0; dd < 64; dd++) s = fmaf(Hs[no*64+dd], HWo[dd*3 + jo], s);
        HD[8+u] = s;
    } else if (t >= 20 && t < 28){            // w_o logits
        int u = t - 20;
        int no = u >> 1, comp = u & 1;
        float s = bw[comp];
        #pragma unroll 8
        for (int dd = 0; dd < 64; dd++) s = fmaf(Hs[no*64+dd], HWw[dd*2 + comp], s);
        HD[20+u] = s;
    }
    __syncthreads();

    if (t == 0){
        int tq = p >> 10, hq = (p >> 5) & 31, wq = p & 31;
        float tn = (float)tq * (1.0f/7.0f);
        float hn = (float)hq * (1.0f/31.0f);
        float wn = (float)wq * (1.0f/31.0f);
        float ivt = invsigf_(tn), ivh = invsigf_(hn), ivw = invsigf_(wn);

        #pragma unroll
        for (int no = 0; no < 4; no++){
            float o0 = HD[8+no*3+0], o1 = HD[8+no*3+1], o2 = HD[8+no*3+2];
            float st = sigmoidf_(ivt + o0)*2.0f - 1.0f;
            float sh = sigmoidf_(ivh + o1)*2.0f - 1.0f;
            float sw = sigmoidf_(ivw + o2)*2.0f - 1.0f;
            SPx[no] = ((st + 1.0f)*32.0f - 1.0f)*0.5f;
            SPy[no] = ((sh + 1.0f)*32.0f - 1.0f)*0.5f;
            SPz[no] = ((sw + 1.0f)*8.0f  - 1.0f)*0.5f;
            float za = HD[20+no*2], zb = HD[21+no*2];
            SPw[no] = 1.0f/(1.0f + expf(za - zb));
        }

        if (write_next){
            float d0 = sigmoidf_(ivt + HD[0]) * 7.0f;
            float d1 = sigmoidf_(ivh + HD[1]) * 31.0f;
            float d2 = sigmoidf_(ivw + HD[2]) * 31.0f;
            int ni = 1024*(int)rintf(d0) + 32*(int)rintf(d1) + (int)rintf(d2);
            out[FEAT_OUT_ELEMS + rr] = (float)ni;
        }
    }
    __syncthreads();

    // ---- corner dedup (warp 0)
    if (t < 32){
        const unsigned full = 0xffffffffu;
        int lane = t;
        int no = lane >> 3, j = lane & 7;
        float ix = SPx[no], iy = SPy[no], iz = SPz[no];
        float wo = SPw[no];
        float x0f = floorf(ix), y0f = floorf(iy), z0f = floorf(iz);
        int dx = j & 1, dy = (j >> 1) & 1, dz = j >> 2;
        int xi = (int)x0f + dx, yi = (int)y0f + dy, zi = (int)z0f + dz;
        float fx = ix - x0f, fy = iy - y0f, fz = iz - z0f;
        float w = (dx ? fx : 1.0f-fx) * (dy ? fy : 1.0f-fy) * (dz ? fz : 1.0f-fz) * wo;
        bool valid = (xi >= 0) & (xi < W_) & (yi >= 0) & (yi < H_) & (zi >= 0) & (zi < T_);
        if (!valid) w = 0.0f;
        int q = (min(max(zi,0),T_-1)*H_ + min(max(yi,0),H_-1))*W_ + min(max(xi,0),W_-1);

        unsigned mask = __match_any_sync(full, q);
        float wsum = 0.0f;
        #pragma unroll
        for (int s2 = 0; s2 < 32; s2++){
            float wv = __shfl_sync(full, w, s2);
            int   qv = __shfl_sync(full, q, s2);
            if (qv == q) wsum += wv;
        }
        int leader = __ffs(mask) - 1;
        bool is_leader = (lane == leader);
        unsigned bal = __ballot_sync(full, is_leader);
        int pos = __popc(bal & ((1u << lane) - 1u));
        if (is_leader){ cq[pos] = q; cw[pos] = wsum; }
        __syncwarp();
        if (lane == 0){
            int nq = __popc(bal);
            bool found = false;
            for (int j2 = 0; j2 < nq; j2++){
                if (cq[j2] == p){ cw[j2] += 1.0f; found = true; break; }
            }
            if (!found){ cq[nq] = p; cw[nq] = 1.0f; nq++; }
            s_nq = nq;
            g_nq[rr] = nq;
        }
        __syncwarp();
        int nq = s_nq;
        if (lane < nq){
            g_uq[rr*40 + lane] = cq[lane];
            g_uw[rr*40 + lane] = cw[lane];
        }
        if (lane == 33-33){} // no-op
    }
}

// ============================================================
// Kernel 6: table-driven gather + LN, 256 blocks x 512 threads
// ============================================================
__global__ void __launch_bounds__(512, 2)
sample_ln_kernel(const float* __restrict__ feats,
                 const float* __restrict__ gamma,
                 const float* __restrict__ beta,
                 float* __restrict__ out)
{
    int b  = blockIdx.x;           // row = l*64 + n
    int l  = b >> 6;
    int p  = flat_idx(b & 63);
    int tid = threadIdx.x;

    __shared__ int    uq[40];
    __shared__ float  uw[40];
    __shared__ float  partial[256];
    __shared__ float2 sred[16];
    __shared__ int    s_nq;
    __shared__ float  s_mu, s_rstd;

    if (tid == 0) s_nq = g_nq[b];
    __syncthreads();
    int nq = s_nq;
    if (tid < nq){ uq[tid] = g_uq[b*40 + tid]; uw[tid] = g_uw[b*40 + tid]; }
    __syncthreads();

    int col  = tid & 255;
    int half = tid >> 8;
    const float* fb = feats + (size_t)col*(THW_*L_) + l;

    float acc = 0.0f;
    for (int j = half; j < nq; j += 2)
        acc = fmaf(uw[j], __ldg(fb + (size_t)uq[j]*L_), acc);

    if (half) partial[col] = acc;
    __syncthreads();

    float v = 0.0f;
    if (!half) v = acc + partial[col];

    const unsigned full = 0xffffffffu;
    float sx = v, sy = v*v;
    #pragma unroll
    for (int o = 16; o > 0; o >>= 1){
        sx += __shfl_xor_sync(full, sx, o);
        sy += __shfl_xor_sync(full, sy, o);
    }
    int lane = tid & 31, wrp = tid >> 5;
    if (lane == 0) sred[wrp] = make_float2(sx, sy);
    __syncthreads();
    if (tid < 16){
        float2 a = sred[tid];
        #pragma unroll
        for (int o = 8; o > 0; o >>= 1){
            a.x += __shfl_xor_sync(0xffffu, a.x, o);
            a.y += __shfl_xor_sync(0xffffu, a.y, o);
        }
        if (tid == 0){
            float mu  = a.x * (1.0f/256.0f);
            float var = a.y * (1.0f/256.0f) - mu*mu;
            s_mu = mu;
            s_rstd = rsqrtf(var + 1e-5f);
        }
    }
    __syncthreads();

    if (!half){
        float o = (v - s_mu) * s_rstd * gamma[col] + beta[col];
        out[((size_t)col*THW_ + p)*L_ + l] = o;
    }
}

// ============================================================
extern "C" void kernel_launch(void* const* d_in, const int* in_sizes, int n_in,
                              void* d_out, int out_size)
{
    const float* feats = (const float*)d_in[0];
    const float* pos   = (const float*)d_in[1];
    const float* W1    = (const float*)d_in[2];
    const float* b1    = (const float*)d_in[3];
    const float* W2    = (const float*)d_in[4];
    const float* b2    = (const float*)d_in[5];
    const float* Wn    = (const float*)d_in[6];
    const float* bn    = (const float*)d_in[7];
    // d_in[8] = Wl, d_in[9] = bl  (dead: softmax row-sum == 1, LN scale-invariant)
    const float* Woff  = (const float*)d_in[10];
    const float* boff  = (const float*)d_in[11];
    const float* Ww    = (const float*)d_in[12];
    const float* bw    = (const float*)d_in[13];
    const float* gamma = (const float*)d_in[14];
    const float* beta  = (const float*)d_in[15];
    float* out = (float*)d_out;

    int write_next = (out_size >= FEAT_OUT_ELEMS + NROWS) ? 1 : 0;

    const int SM1 = (768*18 + 2*KC*32) * 4;   // 88064 B
    const int SM2 = (256*18 + 2*KC*32) * 4;   // 51200 B

    static int smem_set = 0;
    if (!smem_set){
        cudaFuncSetAttribute(mlp1_kernel, cudaFuncAttributeMaxDynamicSharedMemorySize, SM1);
        cudaFuncSetAttribute(mlp2_kernel, cudaFuncAttributeMaxDynamicSharedMemorySize, SM2);
        smem_set = 1;
    }

    glob_fill_kernel<<<256, 256>>>(feats, beta, (float4*)out);
    xprep_kernel<<<256, 256>>>(feats, pos);
    mlp1_kernel<<<dim3(8,16), 256, SM1>>>(W1, b1);
    mlp2_kernel<<<dim3(8,16), 256, SM2>>>(W2, b2);
    heads_kernel<<<256, 128>>>(Wn, bn, Woff, boff, Ww, bw, out, write_next);
    sample_ln_kernel<<<256, 512>>>(feats, gamma, beta, out);
}

// round 8
// speedup vs baseline: 1.0052x; 1.0052x over previous
#include <cuda_runtime.h>
#include <math.h>

#define C_    256
#define T_    8
#define H_    32
#define W_    32
#define L_    4
#define THW_  8192
#define NROWS 256
#define FEAT_OUT_ELEMS (C_*THW_*L_)   // 2097152
#define KC 128
#define NB 128                         // blocks in fused kernel

// ---- scratch (device globals; no allocation) ----
__device__ float    g_X [NROWS*768];
__device__ float    g_H1[NROWS*256];
__device__ float    g_H2[NROWS*256];
__device__ unsigned g_barrier[2];      // monotonic, never reset (replay-safe)

__constant__ int c_tt[4] = {1,3,4,6};
__constant__ int c_hh[4] = {4,12,19,27};

__device__ __forceinline__ int flat_idx(int n){
    int it = n >> 4, ih = (n >> 2) & 3, iw = n & 3;
    return (c_tt[it]*H_ + c_hh[ih])*W_ + c_hh[iw];
}
__device__ __forceinline__ float sigmoidf_(float x){ return 1.0f/(1.0f+expf(-x)); }
__device__ __forceinline__ float invsigf_(float x){
    return logf(fmaxf(x,1e-5f)/fmaxf(1.0f-x,1e-5f));
}
__device__ __forceinline__ void cp_async16(void* smem_dst, const void* gmem_src){
    unsigned s = (unsigned)__cvta_generic_to_shared(smem_dst);
    asm volatile("cp.async.cg.shared.global [%0], [%1], 16;\n" :: "r"(s), "l"(gmem_src));
}
__device__ __forceinline__ void cp_commit(){ asm volatile("cp.async.commit_group;\n"); }
__device__ __forceinline__ void cp_wait0(){ asm volatile("cp.async.wait_group 0;\n"); }
__device__ __forceinline__ void cp_wait1(){ asm volatile("cp.async.wait_group 1;\n"); }

typedef unsigned long long ull;
__device__ __forceinline__ ull fma2_(ull a, ull b, ull c){
    ull d; asm("fma.rn.f32x2 %0, %1, %2, %3;" : "=l"(d) : "l"(a), "l"(b), "l"(c)); return d;
}
__device__ __forceinline__ ull pack2_(float x, float y){
    ull r; asm("mov.b64 %0, {%1, %2};" : "=l"(r) : "f"(x), "f"(y)); return r;
}
__device__ __forceinline__ float2 unpack2_(ull v){
    float2 r; asm("mov.b64 {%0, %1}, %2;" : "=f"(r.x), "=f"(r.y) : "l"(v)); return r;
}

// Device-wide barrier: monotonic counter, wrap-safe compare, replay-safe.
__device__ __forceinline__ void global_bar(int id){
    __syncthreads();
    if (threadIdx.x == 0){
        __threadfence();
        unsigned old  = atomicAdd(&g_barrier[id], 1u);
        unsigned goal = old - (old % (unsigned)NB) + (unsigned)NB;
        volatile unsigned* p = &g_barrier[id];
        while ((int)(*p - goal) < 0){}
        __threadfence();
    }
    __syncthreads();
}

// ============================================================
// Kernel 1: channel mean + beta fill + materialize X[256][768]
// one block per channel c.
// ============================================================
__global__ void __launch_bounds__(256)
glob_fill_x_kernel(const float* __restrict__ feats, const float* __restrict__ pos,
                   const float* __restrict__ beta, float4* __restrict__ out4)
{
    int c = blockIdx.x;
    int t = threadIdx.x;
    const float4* f4 = reinterpret_cast<const float4*>(feats + (size_t)c * (THW_*L_));
    float4 s = make_float4(0.f,0.f,0.f,0.f);
    for (int i = t; i < THW_; i += 256){
        float4 v = f4[i];
        s.x += v.x; s.y += v.y; s.z += v.z; s.w += v.w;
    }
    // beta fill of this channel's output region
    float b = __ldg(&beta[c]);
    float4 bv = make_float4(b,b,b,b);
    float4* ob = out4 + (size_t)c * THW_;
    for (int i = t; i < THW_; i += 256) ob[i] = bv;

    __shared__ float4 sm[256];
    sm[t] = s;
    __syncthreads();
    for (int o = 128; o > 0; o >>= 1){
        if (t < o){
            float4 a = sm[t], bb = sm[t+o];
            sm[t] = make_float4(a.x+bb.x, a.y+bb.y, a.z+bb.z, a.w+bb.w);
        }
        __syncthreads();
    }
    float4 mean = sm[0];
    const float inv = 1.0f/8192.0f;

    // X rows: thread t = row rr
    int l = t >> 6;
    int p = flat_idx(t & 63);
    float fv = feats[((size_t)c*THW_ + p)*L_ + l];
    float pv = pos  [((size_t)c*THW_ + p)*L_ + l];
    float gv = (l==0 ? mean.x : l==1 ? mean.y : l==2 ? mean.z : mean.w) * inv;
    g_X[t*768 + c]       = fv;
    g_X[t*768 + 256 + c] = pv;
    g_X[t*768 + 512 + c] = gv;
}

// ============================================================
// GEMM phase: O[256,256] = relu(Xg[256,KDIM] @ Wg[KDIM,256] + bias)
// block -> tile: c0 = (b&7)*32, r0 = (b>>3)*16. 4 FFMA2 chains.
// ============================================================
template<int KDIM, bool PRE>
__device__ __forceinline__ void gemm_phase(const float* __restrict__ Xg,
                                           const float* __restrict__ Wg,
                                           const float* __restrict__ bias,
                                           float* __restrict__ Og,
                                           float* Xs, float* WbA, float* WbB)
{
    int t  = threadIdx.x;
    int c0 = (blockIdx.x & 7) * 32;
    int r0 = (blockIdx.x >> 3) * 16;
    constexpr int NCH = KDIM / KC;

    if (PRE){
        #pragma unroll
        for (int u = 0; u < 4; u++){
            int idx4 = t + u*256;
            int kk = idx4 >> 3, j2 = (idx4 & 7)*4;
            cp_async16(WbA + idx4*4, Wg + (size_t)kk*256 + c0 + j2);
        }
        cp_commit();
    }

    // Xs[k*18 + row], rows r0..r0+15
    {
        const float4* X4 = reinterpret_cast<const float4*>(Xg);
        constexpr int K4 = KDIM/4;
        for (int idx4 = t; idx4 < 16*K4; idx4 += 256){
            int row = idx4 / K4;
            int k4  = idx4 - row*K4;
            float4 v = X4[(size_t)(r0+row)*K4 + k4];
            int k = k4*4;
            Xs[(k+0)*18 + row] = v.x;
            Xs[(k+1)*18 + row] = v.y;
            Xs[(k+2)*18 + row] = v.z;
            Xs[(k+3)*18 + row] = v.w;
        }
    }

    int j = t & 31, rp = t >> 5;
    ull a0 = 0ULL, a1 = 0ULL, a2 = 0ULL, a3 = 0ULL;

    #pragma unroll 1
    for (int ch = 0; ch < NCH; ch++){
        float* Wcur = (ch & 1) ? WbB : WbA;
        float* Wnxt = (ch & 1) ? WbA : WbB;
        if (ch + 1 < NCH){
            #pragma unroll
            for (int u = 0; u < 4; u++){
                int idx4 = t + u*256;
                int kk = idx4 >> 3, j2 = (idx4 & 7)*4;
                cp_async16(Wnxt + idx4*4, Wg + (size_t)((ch+1)*KC + kk)*256 + c0 + j2);
            }
            cp_commit();
            cp_wait1();
        } else {
            cp_wait0();
        }
        __syncthreads();
        const float* Xb = Xs + ch*KC*18 + 2*rp;
        #pragma unroll 8
        for (int kk = 0; kk < KC; kk += 4){
            float w0 = Wcur[(kk+0)*32 + j];
            a0 = fma2_(*(const ull*)(Xb + (kk+0)*18), pack2_(w0,w0), a0);
            float w1 = Wcur[(kk+1)*32 + j];
            a1 = fma2_(*(const ull*)(Xb + (kk+1)*18), pack2_(w1,w1), a1);
            float w2 = Wcur[(kk+2)*32 + j];
            a2 = fma2_(*(const ull*)(Xb + (kk+2)*18), pack2_(w2,w2), a2);
            float w3 = Wcur[(kk+3)*32 + j];
            a3 = fma2_(*(const ull*)(Xb + (kk+3)*18), pack2_(w3,w3), a3);
        }
        __syncthreads();
    }

    float2 r0v = unpack2_(a0), r1v = unpack2_(a1), r2v = unpack2_(a2), r3v = unpack2_(a3);
    float bb = __ldg(&bias[c0 + j]);
    float sA = r0v.x + r1v.x + r2v.x + r3v.x + bb;
    float sB = r0v.y + r1v.y + r2v.y + r3v.y + bb;
    int row = r0 + 2*rp;
    Og[(size_t)row*256 + c0 + j]     = fmaxf(sA, 0.f);
    Og[(size_t)(row+1)*256 + c0 + j] = fmaxf(sB, 0.f);
}

// ============================================================
// Kernel 2: fused GEMM1 | GB | GEMM2 | GB | heads | sample_ln
// grid 128 x 256 threads (persistent, co-resident).
// dynamic smem (floats):
//   GEMM1: Xs @0 (768*18=13824), Wb @13824 (2*4096)
//   GEMM2: Xs @0 (256*18=4608),  Wb @22016 (2*4096)
// total 30208 floats = 120832 B
// ============================================================
#define G1_XS 0
#define G1_WB 13824
#define G2_XS 0
#define G2_WB 22016
#define FUSED_SMEM_BYTES (30208*4)

__global__ void __launch_bounds__(256, 1)
fused_kernel(const float* __restrict__ W1, const float* __restrict__ b1,
             const float* __restrict__ W2, const float* __restrict__ b2,
             const float* __restrict__ Wn, const float* __restrict__ bn,
             const float* __restrict__ Woff, const float* __restrict__ boff,
             const float* __restrict__ Ww, const float* __restrict__ bw,
             const float* __restrict__ feats,
             const float* __restrict__ gamma, const float* __restrict__ beta,
             float* __restrict__ out, int write_next)
{
    extern __shared__ float sm[];
    __shared__ float Hs[256];
    __shared__ float HWn[768], HWo[192], HWw[128];
    __shared__ float HD[28];
    __shared__ float SPx[4], SPy[4], SPz[4], SPw[4];
    __shared__ int   cq2[2][40];
    __shared__ float cw2[2][40];
    __shared__ int   nq2[2];
    __shared__ float2 sred[8];
    __shared__ float s_mu, s_rstd;

    int t = threadIdx.x;
    int b = blockIdx.x;

    // ---- phase 1: GEMM1
    gemm_phase<768, true>(g_X, W1, b1, g_H1, sm + G1_XS, sm + G1_WB, sm + G1_WB + 4096);

    // early prefetch of W2 chunk 0 (overlaps barrier)
    {
        int c0 = (b & 7) * 32;
        #pragma unroll
        for (int u = 0; u < 4; u++){
            int idx4 = t + u*256;
            int kk = idx4 >> 3, j2 = (idx4 & 7)*4;
            cp_async16(sm + G2_WB + idx4*4, W2 + (size_t)kk*256 + c0 + j2);
        }
        cp_commit();
    }
    global_bar(0);

    // ---- phase 2: GEMM2
    gemm_phase<256, false>(g_H1, W2, b2, g_H2, sm + G2_XS, sm + G2_WB, sm + G2_WB + 4096);
    global_bar(1);

    // ---- phase 3: heads + dedup for rows 2b, 2b+1 (tables stay in smem)
    for (int k = t; k < 768; k += 256) HWn[k] = Wn[k];
    if (t < 192) HWo[t] = Woff[t];
    if (t < 128) HWw[t] = Ww[t];
    __syncthreads();

    #pragma unroll 1
    for (int r2 = 0; r2 < 2; r2++){
        int rr = b*2 + r2;
        int p  = flat_idx(rr & 63);

        Hs[t] = g_H2[rr*256 + t];
        __syncthreads();

        if (t < 3){                               // nxt
            float s = bn[t];
            #pragma unroll 8
            for (int k = 0; k < 256; k++) s = fmaf(Hs[k], HWn[k*3 + t], s);
            HD[t] = s;
        } else if (t >= 8 && t < 20){             // offsets
            int u = t - 8;
            int no = u / 3, jo = u - no*3;
            float s = boff[jo];
            #pragma unroll 8
            for (int dd = 0; dd < 64; dd++) s = fmaf(Hs[no*64+dd], HWo[dd*3 + jo], s);
            HD[8+u] = s;
        } else if (t >= 20 && t < 28){            // w_o logits
            int u = t - 20;
            int no = u >> 1, comp = u & 1;
            float s = bw[comp];
            #pragma unroll 8
            for (int dd = 0; dd < 64; dd++) s = fmaf(Hs[no*64+dd], HWw[dd*2 + comp], s);
            HD[20+u] = s;
        }
        __syncthreads();

        if (t == 0){
            int tq = p >> 10, hq = (p >> 5) & 31, wq = p & 31;
            float tn = (float)tq * (1.0f/7.0f);
            float hn = (float)hq * (1.0f/31.0f);
            float wn = (float)wq * (1.0f/31.0f);
            float ivt = invsigf_(tn), ivh = invsigf_(hn), ivw = invsigf_(wn);

            #pragma unroll
            for (int no = 0; no < 4; no++){
                float o0 = HD[8+no*3+0], o1 = HD[8+no*3+1], o2 = HD[8+no*3+2];
                float st = sigmoidf_(ivt + o0)*2.0f - 1.0f;
                float sh = sigmoidf_(ivh + o1)*2.0f - 1.0f;
                float sw = sigmoidf_(ivw + o2)*2.0f - 1.0f;
                SPx[no] = ((st + 1.0f)*32.0f - 1.0f)*0.5f;
                SPy[no] = ((sh + 1.0f)*32.0f - 1.0f)*0.5f;
                SPz[no] = ((sw + 1.0f)*8.0f  - 1.0f)*0.5f;
                float za = HD[20+no*2], zb = HD[21+no*2];
                SPw[no] = 1.0f/(1.0f + expf(za - zb));
            }

            if (write_next){
                float d0 = sigmoidf_(ivt + HD[0]) * 7.0f;
                float d1 = sigmoidf_(ivh + HD[1]) * 31.0f;
                float d2 = sigmoidf_(ivw + HD[2]) * 31.0f;
                int ni = 1024*(int)rintf(d0) + 32*(int)rintf(d1) + (int)rintf(d2);
                out[FEAT_OUT_ELEMS + rr] = (float)ni;
            }
        }
        __syncthreads();

        if (t < 32){
            const unsigned full = 0xffffffffu;
            int lane = t;
            int no = lane >> 3, j = lane & 7;
            float ix = SPx[no], iy = SPy[no], iz = SPz[no];
            float wo = SPw[no];
            float x0f = floorf(ix), y0f = floorf(iy), z0f = floorf(iz);
            int dx = j & 1, dy = (j >> 1) & 1, dz = j >> 2;
            int xi = (int)x0f + dx, yi = (int)y0f + dy, zi = (int)z0f + dz;
            float fx = ix - x0f, fy = iy - y0f, fz = iz - z0f;
            float w = (dx ? fx : 1.0f-fx) * (dy ? fy : 1.0f-fy) * (dz ? fz : 1.0f-fz) * wo;
            bool valid = (xi >= 0) & (xi < W_) & (yi >= 0) & (yi < H_) & (zi >= 0) & (zi < T_);
            if (!valid) w = 0.0f;
            int q = (min(max(zi,0),T_-1)*H_ + min(max(yi,0),H_-1))*W_ + min(max(xi,0),W_-1);

            unsigned mask = __match_any_sync(full, q);
            float wsum = 0.0f;
            #pragma unroll
            for (int s2 = 0; s2 < 32; s2++){
                float wv = __shfl_sync(full, w, s2);
                int   qv = __shfl_sync(full, q, s2);
                if (qv == q) wsum += wv;
            }
            int leader = __ffs(mask) - 1;
            bool is_leader = (lane == leader);
            unsigned bal = __ballot_sync(full, is_leader);
            int pos = __popc(bal & ((1u << lane) - 1u));
            if (is_leader){ cq2[r2][pos] = q; cw2[r2][pos] = wsum; }
            __syncwarp();
            if (lane == 0){
                int nq = __popc(bal);
                bool found = false;
                for (int j2 = 0; j2 < nq; j2++){
                    if (cq2[r2][j2] == p){ cw2[r2][j2] += 1.0f; found = true; break; }
                }
                if (!found){ cq2[r2][nq] = p; cw2[r2][nq] = 1.0f; nq++; }
                nq2[r2] = nq;
            }
        }
        __syncthreads();
    }

    // ---- phase 4: sample + LN for rows 2b, 2b+1 (tables already in smem)
    #pragma unroll 1
    for (int r2 = 0; r2 < 2; r2++){
        int rr = b*2 + r2;
        int l  = rr >> 6;
        int p  = flat_idx(rr & 63);
        int nq = nq2[r2];

        int c = t;
        const float* fb = feats + (size_t)c*(THW_*L_) + l;
        float acc = 0.0f;
        #pragma unroll 4
        for (int j2 = 0; j2 < nq; j2++)
            acc = fmaf(cw2[r2][j2], __ldg(fb + (size_t)cq2[r2][j2]*L_), acc);
        float v = acc;

        const unsigned full = 0xffffffffu;
        float sx = v, sy = v*v;
        #pragma unroll
        for (int o = 16; o > 0; o >>= 1){
            sx += __shfl_xor_sync(full, sx, o);
            sy += __shfl_xor_sync(full, sy, o);
        }
        int lane = t & 31, wrp = t >> 5;
        if (lane == 0) sred[wrp] = make_float2(sx, sy);
        __syncthreads();
        if (t < 8){
            float2 a = sred[t];
            #pragma unroll
            for (int o = 4; o > 0; o >>= 1){
                a.x += __shfl_xor_sync(0xffu, a.x, o);
                a.y += __shfl_xor_sync(0xffu, a.y, o);
            }
            if (t == 0){
                float mu  = a.x * (1.0f/256.0f);
                float var = a.y * (1.0f/256.0f) - mu*mu;
                s_mu = mu;
                s_rstd = rsqrtf(var + 1e-5f);
            }
        }
        __syncthreads();

        float o = (v - s_mu) * s_rstd * __ldg(&gamma[c]) + __ldg(&beta[c]);
        out[((size_t)c*THW_ + p)*L_ + l] = o;
        __syncthreads();
    }
}

// ============================================================
extern "C" void kernel_launch(void* const* d_in, const int* in_sizes, int n_in,
                              void* d_out, int out_size)
{
    const float* feats = (const float*)d_in[0];
    const float* pos   = (const float*)d_in[1];
    const float* W1    = (const float*)d_in[2];
    const float* b1    = (const float*)d_in[3];
    const float* W2    = (const float*)d_in[4];
    const float* b2    = (const float*)d_in[5];
    const float* Wn    = (const float*)d_in[6];
    const float* bn    = (const float*)d_in[7];
    // d_in[8]=Wl, d_in[9]=bl dead (softmax row-sum == 1; LN scale-invariant)
    const float* Woff  = (const float*)d_in[10];
    const float* boff  = (const float*)d_in[11];
    const float* Ww    = (const float*)d_in[12];
    const float* bw    = (const float*)d_in[13];
    const float* gamma = (const float*)d_in[14];
    const float* beta  = (const float*)d_in[15];
    float* out = (float*)d_out;

    int write_next = (out_size >= FEAT_OUT_ELEMS + NROWS) ? 1 : 0;

    static int smem_set = 0;
    if (!smem_set){
        cudaFuncSetAttribute(fused_kernel, cudaFuncAttributeMaxDynamicSharedMemorySize,
                             FUSED_SMEM_BYTES);
        smem_set = 1;
    }

    glob_fill_x_kernel<<<256, 256>>>(feats, pos, beta, (float4*)out);
    fused_kernel<<<NB, 256, FUSED_SMEM_BYTES>>>(W1, b1, W2, b2, Wn, bn, Woff, boff,
                                                Ww, bw, feats, gamma, beta, out, write_next);
}

// round 9
// speedup vs baseline: 1.1471x; 1.1412x over previous
#include <cuda_runtime.h>
#include <math.h>

#define C_    256
#define T_    8
#define H_    32
#define W_    32
#define L_    4
#define THW_  8192
#define NROWS 256
#define FEAT_OUT_ELEMS (C_*THW_*L_)   // 2097152
#define NB 128

// ---- scratch (device globals; no allocation) ----
__device__ float    g_XT [768*256];    // X transposed: [k][row]
__device__ float    g_H1T[256*256];    // H1 transposed: [k][row]
__device__ float    g_H2 [256*256];    // H2 row-major: [row][c]
__device__ unsigned g_barrier[2];      // monotonic, never reset (replay-safe)

__constant__ int c_tt[4] = {1,3,4,6};
__constant__ int c_hh[4] = {4,12,19,27};

__device__ __forceinline__ int flat_idx(int n){
    int it = n >> 4, ih = (n >> 2) & 3, iw = n & 3;
    return (c_tt[it]*H_ + c_hh[ih])*W_ + c_hh[iw];
}
__device__ __forceinline__ float sigmoidf_(float x){ return 1.0f/(1.0f+expf(-x)); }
__device__ __forceinline__ float invsigf_(float x){
    return logf(fmaxf(x,1e-5f)/fmaxf(1.0f-x,1e-5f));
}
__device__ __forceinline__ void cp_async16(void* smem_dst, const void* gmem_src){
    unsigned s = (unsigned)__cvta_generic_to_shared(smem_dst);
    asm volatile("cp.async.cg.shared.global [%0], [%1], 16;\n" :: "r"(s), "l"(gmem_src));
}
__device__ __forceinline__ void cp_commit(){ asm volatile("cp.async.commit_group;\n"); }
__device__ __forceinline__ void cp_wait0(){ asm volatile("cp.async.wait_group 0;\n"); }
__device__ __forceinline__ void cp_wait1(){ asm volatile("cp.async.wait_group 1;\n"); }

typedef unsigned long long ull;
__device__ __forceinline__ ull fma2_(ull a, ull b, ull c){
    ull d; asm("fma.rn.f32x2 %0, %1, %2, %3;" : "=l"(d) : "l"(a), "l"(b), "l"(c)); return d;
}
__device__ __forceinline__ ull pack2_(float x, float y){
    ull r; asm("mov.b64 %0, {%1, %2};" : "=l"(r) : "f"(x), "f"(y)); return r;
}
__device__ __forceinline__ float2 unpack2_(ull v){
    float2 r; asm("mov.b64 {%0, %1}, %2;" : "=f"(r.x), "=f"(r.y) : "l"(v)); return r;
}

// Device-wide barrier: monotonic counter, wrap-safe, replay-safe.
__device__ __forceinline__ void global_bar(int id){
    __syncthreads();
    if (threadIdx.x == 0){
        __threadfence();
        unsigned old  = atomicAdd(&g_barrier[id], 1u);
        unsigned goal = old - (old % (unsigned)NB) + (unsigned)NB;
        volatile unsigned* p = &g_barrier[id];
        while ((int)(*p - goal) < 0){}
        __threadfence();
    }
    __syncthreads();
}

// ============================================================
// Kernel 1: channel mean + materialize XT[768][256] (k-major)
// one block per channel c, 512 threads.
// ============================================================
__global__ void __launch_bounds__(512)
prep_kernel(const float* __restrict__ feats, const float* __restrict__ pos)
{
    int c = blockIdx.x;
    int t = threadIdx.x;
    const float4* f4 = reinterpret_cast<const float4*>(feats + (size_t)c * (THW_*L_));
    float4 s = make_float4(0.f,0.f,0.f,0.f);
    for (int i = t; i < THW_; i += 512){
        float4 v = f4[i];
        s.x += v.x; s.y += v.y; s.z += v.z; s.w += v.w;
    }
    __shared__ float4 sm[512];
    sm[t] = s;
    __syncthreads();
    for (int o = 256; o > 0; o >>= 1){
        if (t < o){
            float4 a = sm[t], bb = sm[t+o];
            sm[t] = make_float4(a.x+bb.x, a.y+bb.y, a.z+bb.z, a.w+bb.w);
        }
        __syncthreads();
    }
    if (t < 256){
        float4 mean = sm[0];
        const float inv = 1.0f/8192.0f;
        int l = t >> 6;
        int p = flat_idx(t & 63);
        float fv = feats[((size_t)c*THW_ + p)*L_ + l];
        float pv = pos  [((size_t)c*THW_ + p)*L_ + l];
        float gv = (l==0 ? mean.x : l==1 ? mean.y : l==2 ? mean.z : mean.w) * inv;
        g_XT[(size_t)c*256 + t]       = fv;
        g_XT[(size_t)(256+c)*256 + t] = pv;
        g_XT[(size_t)(512+c)*256 + t] = gv;
    }
}

// ============================================================
// GEMM phase: Out = relu(X[256,K] @ W[K,256] + bias)
// X given k-major (XT[k][256]). 128 blocks x 512 threads.
// block tile 16 rows x 32 cols; thread = (j=col, rp=row-pair, h=k-half).
// inner loop: LDS.64 xpair + LDS.64 wdup + FFMA2  (3 instrs / k)
// ============================================================
#define WD_STRIDE 33        // ull stride per k in Wdup
#define WD_BUF    (128*WD_STRIDE)
#define XS_BUF    2048      // floats per X chunk buffer (128k x 16 rows)

template<int NCH, bool WRITE_T>
__device__ __forceinline__ void gemm_phase(
    const float* __restrict__ XT, const float* __restrict__ Wg,
    const float* __restrict__ bias, float* __restrict__ Out,
    ull* Wd, float* Xs, ull* PART)
{
    int t  = threadIdx.x;
    int c0 = (blockIdx.x & 7) * 32;
    int r0 = (blockIdx.x >> 3) * 16;
    int j  = t & 31;
    int rp = (t >> 5) & 7;
    int h  = t >> 8;
    int kq = t >> 2, seg = t & 3;      // fill indices: k-row 0..127, segment 0..3

    // ---- prime: cp X chunk 0, LDG W chunk 0, STS dup
    cp_async16(Xs + kq*16 + seg*4, XT + (size_t)kq*256 + r0 + seg*4);
    cp_commit();
    float4 wA, wB;
    {
        const float* src = Wg + (size_t)kq*256 + c0 + seg*8;
        wA = *(const float4*)src; wB = *(const float4*)(src+4);
    }
    {
        ull* dst = Wd + kq*WD_STRIDE + seg*8;
        dst[0]=pack2_(wA.x,wA.x); dst[1]=pack2_(wA.y,wA.y);
        dst[2]=pack2_(wA.z,wA.z); dst[3]=pack2_(wA.w,wA.w);
        dst[4]=pack2_(wB.x,wB.x); dst[5]=pack2_(wB.y,wB.y);
        dst[6]=pack2_(wB.z,wB.z); dst[7]=pack2_(wB.w,wB.w);
    }

    ull a0=0ULL, a1=0ULL, a2=0ULL, a3=0ULL;

    #pragma unroll 1
    for (int ch = 0; ch < NCH; ch++){
        float* Xc = Xs + (ch & 1)*XS_BUF;
        ull*   Wc = Wd + (ch & 1)*WD_BUF;
        if (ch + 1 < NCH){
            float* Xn = Xs + ((ch+1) & 1)*XS_BUF;
            cp_async16(Xn + kq*16 + seg*4,
                       XT + (size_t)((ch+1)*128 + kq)*256 + r0 + seg*4);
            cp_commit();
            const float* src = Wg + (size_t)((ch+1)*128 + kq)*256 + c0 + seg*8;
            wA = *(const float4*)src; wB = *(const float4*)(src+4);
            cp_wait1();
        } else {
            cp_wait0();
        }
        __syncthreads();

        const float* Xb = Xc + h*(64*16) + 2*rp;
        const ull*   Wb = Wc + h*(64*WD_STRIDE) + j;
        #pragma unroll 8
        for (int kk = 0; kk < 64; kk += 4){
            a0 = fma2_(*(const ull*)(Xb + (kk+0)*16), Wb[(kk+0)*WD_STRIDE], a0);
            a1 = fma2_(*(const ull*)(Xb + (kk+1)*16), Wb[(kk+1)*WD_STRIDE], a1);
            a2 = fma2_(*(const ull*)(Xb + (kk+2)*16), Wb[(kk+2)*WD_STRIDE], a2);
            a3 = fma2_(*(const ull*)(Xb + (kk+3)*16), Wb[(kk+3)*WD_STRIDE], a3);
        }
        __syncthreads();

        if (ch + 1 < NCH){
            ull* dst = Wd + ((ch+1) & 1)*WD_BUF + kq*WD_STRIDE + seg*8;
            dst[0]=pack2_(wA.x,wA.x); dst[1]=pack2_(wA.y,wA.y);
            dst[2]=pack2_(wA.z,wA.z); dst[3]=pack2_(wA.w,wA.w);
            dst[4]=pack2_(wB.x,wB.x); dst[5]=pack2_(wB.y,wB.y);
            dst[6]=pack2_(wB.z,wB.z); dst[7]=pack2_(wB.w,wB.w);
        }
    }

    float2 e0 = unpack2_(a0), e1 = unpack2_(a1), e2 = unpack2_(a2), e3 = unpack2_(a3);
    float2 s2 = make_float2(e0.x+e1.x+e2.x+e3.x, e0.y+e1.y+e2.y+e3.y);
    if (h == 1) PART[rp*32 + j] = pack2_(s2.x, s2.y);
    __syncthreads();
    if (h == 0){
        float2 pp = unpack2_(PART[rp*32 + j]);
        float bb = __ldg(&bias[c0 + j]);
        float v0 = fmaxf(s2.x + pp.x + bb, 0.f);
        float v1 = fmaxf(s2.y + pp.y + bb, 0.f);
        if (WRITE_T){   // Out[k][row] transposed
            *(float2*)(Out + (size_t)(c0 + j)*256 + r0 + 2*rp) = make_float2(v0, v1);
        } else {        // Out[row][c]
            Out[(size_t)(r0 + 2*rp  )*256 + c0 + j] = v0;
            Out[(size_t)(r0 + 2*rp+1)*256 + c0 + j] = v1;
        }
    }
    __syncthreads();
}

// ============================================================
// Kernel 2: fused fill | GEMM1 | GB | GEMM2 | GB | heads | sample_ln
// grid 128 x 512 threads. dynamic smem = 86016 B.
// ============================================================
#define FUSED_SMEM_BYTES 86016

__global__ void __launch_bounds__(512, 1)
fused_kernel(const float* __restrict__ W1, const float* __restrict__ b1,
             const float* __restrict__ W2, const float* __restrict__ b2,
             const float* __restrict__ Wn, const float* __restrict__ bn,
             const float* __restrict__ Woff, const float* __restrict__ boff,
             const float* __restrict__ Ww, const float* __restrict__ bw,
             const float* __restrict__ feats,
             const float* __restrict__ gamma, const float* __restrict__ beta,
             float* __restrict__ out, int write_next)
{
    extern __shared__ ull smu[];
    ull*   Wd   = smu;                       // 2 * 4224 ull
    float* Xs   = (float*)(smu + 2*WD_BUF);  // 2 * 2048 floats
    ull*   PART = smu + 2*WD_BUF + 1024;     // 256 ull

    __shared__ float  Hs2[2][256];
    __shared__ float  HWn[768], HWo[192], HWw[128];
    __shared__ float  HD2[2][28];
    __shared__ float  SPx[2][4], SPy[2][4], SPz[2][4], SPw[2][4];
    __shared__ int    cq2[2][40];
    __shared__ float  cw2[2][40];
    __shared__ int    nq2[2];
    __shared__ float2 sred2[2][8];
    __shared__ float  s_mu[2], s_rstd[2];

    int t = threadIdx.x;
    int b = blockIdx.x;

    // ---- phase 0: beta fill (skips sampled positions), overlaps GEMM
    {
        float4* out4 = (float4*)out;
        const unsigned tm = 0x5Au;                               // t in {1,3,4,6}
        const unsigned hm = (1u<<4)|(1u<<12)|(1u<<19)|(1u<<27);  // h,w in {4,12,19,27}
        #pragma unroll
        for (int u = 0; u < 8; u++){
            int f = b*4096 + u*512 + t;        // float4 index over 524288
            int c = f >> 13;
            int p = f & 8191;
            int t3 = p >> 10, h3 = (p >> 5) & 31, w3 = p & 31;
            bool samp = ((tm >> t3) & 1u) && ((hm >> h3) & 1u) && ((hm >> w3) & 1u);
            if (!samp){
                float bb = __ldg(&beta[c]);
                out4[f] = make_float4(bb, bb, bb, bb);
            }
        }
    }

    // ---- phase 1: GEMM1 (K=768) -> g_H1T
    gemm_phase<6, true>(g_XT, W1, b1, g_H1T, Wd, Xs, PART);
    global_bar(0);

    // ---- phase 2: GEMM2 (K=256) -> g_H2
    gemm_phase<2, false>(g_H1T, W2, b2, g_H2, Wd, Xs, PART);
    global_bar(1);

    // ---- phase 3: heads + dedup, both rows concurrently
    int row = t >> 8;          // 0/1
    int u   = t & 255;
    int rr  = b*2 + row;
    int p   = flat_idx(rr & 63);

    Hs2[row][u] = g_H2[(size_t)rr*256 + u];
    for (int k = t; k < 768; k += 512) HWn[k] = Wn[k];
    if (t < 192) HWo[t] = Woff[t];
    if (t >= 256 && t < 384) HWw[t-256] = Ww[t-256];
    __syncthreads();

    if (u < 3){                               // nxt
        float s = bn[u];
        #pragma unroll 8
        for (int k = 0; k < 256; k++) s = fmaf(Hs2[row][k], HWn[k*3 + u], s);
        HD2[row][u] = s;
    } else if (u >= 8 && u < 20){             // offsets
        int v = u - 8;
        int no = v / 3, jo = v - no*3;
        float s = boff[jo];
        #pragma unroll 8
        for (int dd = 0; dd < 64; dd++) s = fmaf(Hs2[row][no*64+dd], HWo[dd*3 + jo], s);
        HD2[row][8+v] = s;
    } else if (u >= 20 && u < 28){            // w_o logits
        int v = u - 20;
        int no = v >> 1, comp = v & 1;
        float s = bw[comp];
        #pragma unroll 8
        for (int dd = 0; dd < 64; dd++) s = fmaf(Hs2[row][no*64+dd], HWw[dd*2 + comp], s);
        HD2[row][20+v] = s;
    }
    __syncthreads();

    if (u == 0){
        int tq = p >> 10, hq = (p >> 5) & 31, wq = p & 31;
        float tn = (float)tq * (1.0f/7.0f);
        float hn = (float)hq * (1.0f/31.0f);
        float wn = (float)wq * (1.0f/31.0f);
        float ivt = invsigf_(tn), ivh = invsigf_(hn), ivw = invsigf_(wn);

        #pragma unroll
        for (int no = 0; no < 4; no++){
            float o0 = HD2[row][8+no*3+0], o1 = HD2[row][8+no*3+1], o2 = HD2[row][8+no*3+2];
            float st = sigmoidf_(ivt + o0)*2.0f - 1.0f;
            float sh = sigmoidf_(ivh + o1)*2.0f - 1.0f;
            float sw = sigmoidf_(ivw + o2)*2.0f - 1.0f;
            SPx[row][no] = ((st + 1.0f)*32.0f - 1.0f)*0.5f;
            SPy[row][no] = ((sh + 1.0f)*32.0f - 1.0f)*0.5f;
            SPz[row][no] = ((sw + 1.0f)*8.0f  - 1.0f)*0.5f;
            float za = HD2[row][20+no*2], zb = HD2[row][21+no*2];
            SPw[row][no] = 1.0f/(1.0f + expf(za - zb));
        }

        if (write_next){
            float d0 = sigmoidf_(ivt + HD2[row][0]) * 7.0f;
            float d1 = sigmoidf_(ivh + HD2[row][1]) * 31.0f;
            float d2 = sigmoidf_(ivw + HD2[row][2]) * 31.0f;
            int ni = 1024*(int)rintf(d0) + 32*(int)rintf(d1) + (int)rintf(d2);
            out[FEAT_OUT_ELEMS + rr] = (float)ni;
        }
    }
    __syncthreads();

    if (u < 32){   // warp 0 (row 0) and warp 8 (row 1): full warps
        const unsigned full = 0xffffffffu;
        int lane = t & 31;
        int no = lane >> 3, jj = lane & 7;
        float ix = SPx[row][no], iy = SPy[row][no], iz = SPz[row][no];
        float wo = SPw[row][no];
        float x0f = floorf(ix), y0f = floorf(iy), z0f = floorf(iz);
        int dx = jj & 1, dy = (jj >> 1) & 1, dz = jj >> 2;
        int xi = (int)x0f + dx, yi = (int)y0f + dy, zi = (int)z0f + dz;
        float fx = ix - x0f, fy = iy - y0f, fz = iz - z0f;
        float w = (dx ? fx : 1.0f-fx) * (dy ? fy : 1.0f-fy) * (dz ? fz : 1.0f-fz) * wo;
        bool valid = (xi >= 0) & (xi < W_) & (yi >= 0) & (yi < H_) & (zi >= 0) & (zi < T_);
        if (!valid) w = 0.0f;
        int q = (min(max(zi,0),T_-1)*H_ + min(max(yi,0),H_-1))*W_ + min(max(xi,0),W_-1);

        unsigned mask = __match_any_sync(full, q);
        float wsum = 0.0f;
        #pragma unroll
        for (int s2 = 0; s2 < 32; s2++){
            float wv = __shfl_sync(full, w, s2);
            int   qv = __shfl_sync(full, q, s2);
            if (qv == q) wsum += wv;
        }
        int leader = __ffs(mask) - 1;
        bool is_leader = (lane == leader);
        unsigned bal = __ballot_sync(full, is_leader);
        int pos = __popc(bal & ((1u << lane) - 1u));
        if (is_leader){ cq2[row][pos] = q; cw2[row][pos] = wsum; }
        __syncwarp();
        if (lane == 0){
            int nq = __popc(bal);
            bool found = false;
            for (int j2 = 0; j2 < nq; j2++){
                if (cq2[row][j2] == p){ cw2[row][j2] += 1.0f; found = true; break; }
            }
            if (!found){ cq2[row][nq] = p; cw2[row][nq] = 1.0f; nq++; }
            nq2[row] = nq;
        }
    }
    __syncthreads();

    // ---- phase 4: sample + LN, both rows concurrently
    {
        int l  = rr >> 6;
        int c  = u;
        int nq = nq2[row];
        const float* fb = feats + (size_t)c*(THW_*L_) + l;
        float acc = 0.0f;
        #pragma unroll 4
        for (int j2 = 0; j2 < nq; j2++)
            acc = fmaf(cw2[row][j2], __ldg(fb + (size_t)cq2[row][j2]*L_), acc);
        float v = acc;

        const unsigned full = 0xffffffffu;
        float sx = v, sy = v*v;
        #pragma unroll
        for (int o = 16; o > 0; o >>= 1){
            sx += __shfl_xor_sync(full, sx, o);
            sy += __shfl_xor_sync(full, sy, o);
        }
        int lane = t & 31;
        int wrp  = (t >> 5) & 7;
        if (lane == 0) sred2[row][wrp] = make_float2(sx, sy);
        __syncthreads();
        if (u == 0){
            float mx = 0.f, my = 0.f;
            #pragma unroll
            for (int k = 0; k < 8; k++){ mx += sred2[row][k].x; my += sred2[row][k].y; }
            float mu  = mx * (1.0f/256.0f);
            float var = my * (1.0f/256.0f) - mu*mu;
            s_mu[row] = mu;
            s_rstd[row] = rsqrtf(var + 1e-5f);
        }
        __syncthreads();

        float o = (v - s_mu[row]) * s_rstd[row] * __ldg(&gamma[c]) + __ldg(&beta[c]);
        out[((size_t)c*THW_ + p)*L_ + l] = o;
    }
}

// ============================================================
extern "C" void kernel_launch(void* const* d_in, const int* in_sizes, int n_in,
                              void* d_out, int out_size)
{
    const float* feats = (const float*)d_in[0];
    const float* pos   = (const float*)d_in[1];
    const float* W1    = (const float*)d_in[2];
    const float* b1    = (const float*)d_in[3];
    const float* W2    = (const float*)d_in[4];
    const float* b2    = (const float*)d_in[5];
    const float* Wn    = (const float*)d_in[6];
    const float* bn    = (const float*)d_in[7];
    // d_in[8]=Wl, d_in[9]=bl dead (softmax row-sum == 1; LN scale-invariant)
    const float* Woff  = (const float*)d_in[10];
    const float* boff  = (const float*)d_in[11];
    const float* Ww    = (const float*)d_in[12];
    const float* bw    = (const float*)d_in[13];
    const float* gamma = (const float*)d_in[14];
    const float* beta  = (const float*)d_in[15];
    float* out = (float*)d_out;

    int write_next = (out_size >= FEAT_OUT_ELEMS + NROWS) ? 1 : 0;

    static int smem_set = 0;
    if (!smem_set){
        cudaFuncSetAttribute(fused_kernel, cudaFuncAttributeMaxDynamicSharedMemorySize,
                             FUSED_SMEM_BYTES);
        smem_set = 1;
    }

    prep_kernel<<<256, 512>>>(feats, pos);
    fused_kernel<<<NB, 512, FUSED_SMEM_BYTES>>>(W1, b1, W2, b2, Wn, bn, Woff, boff,
                                                Ww, bw, feats, gamma, beta, out, write_next);
}

// round 10
// speedup vs baseline: 1.4016x; 1.2219x over previous
#include <cuda_runtime.h>
#include <math.h>

#define C_    256
#define T_    8
#define H_    32
#define W_    32
#define L_    4
#define THW_  8192
#define NROWS 256
#define FEAT_OUT_ELEMS (C_*THW_*L_)   // 2097152
#define NB 128

// ---- scratch (device globals; no allocation) ----
__device__ float    g_XT [768*256];    // X transposed: [k][row]
__device__ float    g_H1T[256*256];    // H1 transposed: [k][row]
__device__ float    g_H2 [256*256];    // H2 row-major: [row][c]
__device__ unsigned g_barrier[2];      // monotonic, never reset (replay-safe)

__constant__ int c_tt[4] = {1,3,4,6};
__constant__ int c_hh[4] = {4,12,19,27};

__device__ __forceinline__ int flat_idx(int n){
    int it = n >> 4, ih = (n >> 2) & 3, iw = n & 3;
    return (c_tt[it]*H_ + c_hh[ih])*W_ + c_hh[iw];
}
__device__ __forceinline__ float sigmoidf_(float x){ return 1.0f/(1.0f+expf(-x)); }
__device__ __forceinline__ float invsigf_(float x){
    return logf(fmaxf(x,1e-5f)/fmaxf(1.0f-x,1e-5f));
}
__device__ __forceinline__ void cp_async16(void* smem_dst, const void* gmem_src){
    unsigned s = (unsigned)__cvta_generic_to_shared(smem_dst);
    asm volatile("cp.async.cg.shared.global [%0], [%1], 16;\n" :: "r"(s), "l"(gmem_src));
}
__device__ __forceinline__ void cp_commit(){ asm volatile("cp.async.commit_group;\n"); }
__device__ __forceinline__ void cp_wait0(){ asm volatile("cp.async.wait_group 0;\n"); }
__device__ __forceinline__ void cp_wait1(){ asm volatile("cp.async.wait_group 1;\n"); }

typedef unsigned long long ull;
__device__ __forceinline__ ull fma2_(ull a, ull b, ull c){
    ull d; asm("fma.rn.f32x2 %0, %1, %2, %3;" : "=l"(d) : "l"(a), "l"(b), "l"(c)); return d;
}
__device__ __forceinline__ ull pack2_(float x, float y){
    ull r; asm("mov.b64 %0, {%1, %2};" : "=l"(r) : "f"(x), "f"(y)); return r;
}
__device__ __forceinline__ float2 unpack2_(ull v){
    float2 r; asm("mov.b64 {%0, %1}, %2;" : "=f"(r.x), "=f"(r.y) : "l"(v)); return r;
}

// Device-wide barrier: monotonic counter, wrap-safe, replay-safe.
__device__ __forceinline__ void global_bar(int id){
    __syncthreads();
    if (threadIdx.x == 0){
        __threadfence();
        unsigned old  = atomicAdd(&g_barrier[id], 1u);
        unsigned goal = old - (old % (unsigned)NB) + (unsigned)NB;
        volatile unsigned* p = &g_barrier[id];
        while ((int)(*p - goal) < 0){}
        __threadfence();
    }
    __syncthreads();
}

// ============================================================
// Kernel 1: channel mean + materialize XT[768][256] (k-major)
// ============================================================
__global__ void __launch_bounds__(512)
prep_kernel(const float* __restrict__ feats, const float* __restrict__ pos)
{
    int c = blockIdx.x;
    int t = threadIdx.x;
    const float4* f4 = reinterpret_cast<const float4*>(feats + (size_t)c * (THW_*L_));
    float4 s = make_float4(0.f,0.f,0.f,0.f);
    for (int i = t; i < THW_; i += 512){
        float4 v = f4[i];
        s.x += v.x; s.y += v.y; s.z += v.z; s.w += v.w;
    }
    __shared__ float4 sm[512];
    sm[t] = s;
    __syncthreads();
    for (int o = 256; o > 0; o >>= 1){
        if (t < o){
            float4 a = sm[t], bb = sm[t+o];
            sm[t] = make_float4(a.x+bb.x, a.y+bb.y, a.z+bb.z, a.w+bb.w);
        }
        __syncthreads();
    }
    if (t < 256){
        float4 mean = sm[0];
        const float inv = 1.0f/8192.0f;
        int l = t >> 6;
        int p = flat_idx(t & 63);
        float fv = feats[((size_t)c*THW_ + p)*L_ + l];
        float pv = pos  [((size_t)c*THW_ + p)*L_ + l];
        float gv = (l==0 ? mean.x : l==1 ? mean.y : l==2 ? mean.z : mean.w) * inv;
        g_XT[(size_t)c*256 + t]       = fv;
        g_XT[(size_t)(256+c)*256 + t] = pv;
        g_XT[(size_t)(512+c)*256 + t] = gv;
    }
}

// ============================================================
// GEMM phase (register-tiled): Out = relu(X[256,K] @ W[K,256] + bias)
// X given k-major (XT[k][256]). grid 128, 512 threads.
// tile 16r x 32c; thread = (rp=row-pair, qc=col-quad, ks=k-split/8).
// per k: LDS.128 xdup-pair + LDS.128 w-quad + 4 FFMA2  (8 MACs).
// smem: Xd[2][2048] ull (x pre-dup), Wf[2][4096] float. PART aliases Xd[0].
// ============================================================
#define XD_ULL 2048
#define WF_F   4096

template<int NCH, bool WRITE_T>
__device__ __forceinline__ void gemm_phase(
    const float* __restrict__ XT, const float* __restrict__ Wg,
    const float* __restrict__ bias, float* __restrict__ Out,
    ull* Xd, float* Wf)
{
    int t  = threadIdx.x;
    int c0 = (blockIdx.x & 7) * 32;
    int r0 = (blockIdx.x >> 3) * 16;
    int rp = t & 7, qc = (t >> 3) & 7, ks = t >> 6;
    int kk = t >> 2, seg = t & 3;          // fill: k-row 0..127, row-seg 0..3

    // ---- prime chunk 0
    {
        #pragma unroll
        for (int u = 0; u < 2; u++){
            int idx4 = t + u*512;
            int wk = idx4 >> 3, ws = idx4 & 7;
            cp_async16(Wf + wk*32 + ws*4, Wg + (size_t)wk*256 + c0 + ws*4);
        }
        cp_commit();
        float4 xv = *(const float4*)(XT + (size_t)kk*256 + r0 + seg*4);
        ull* dst = Xd + kk*16 + seg*4;
        ulonglong2 d0, d1;
        d0.x = pack2_(xv.x, xv.x); d0.y = pack2_(xv.y, xv.y);
        d1.x = pack2_(xv.z, xv.z); d1.y = pack2_(xv.w, xv.w);
        *(ulonglong2*)dst = d0;
        *(ulonglong2*)(dst+2) = d1;
    }

    ull aA0=0ULL, aA1=0ULL, aB0=0ULL, aB1=0ULL;
    float4 xn;

    #pragma unroll 1
    for (int ch = 0; ch < NCH; ch++){
        ull*   Xc = Xd + (ch & 1)*XD_ULL;
        float* Wc = Wf + (ch & 1)*WF_F;
        if (ch + 1 < NCH){
            float* Wn2 = Wf + ((ch+1)&1)*WF_F;
            #pragma unroll
            for (int u = 0; u < 2; u++){
                int idx4 = t + u*512;
                int wk = idx4 >> 3, ws = idx4 & 7;
                cp_async16(Wn2 + wk*32 + ws*4,
                           Wg + (size_t)((ch+1)*128 + wk)*256 + c0 + ws*4);
            }
            cp_commit();
            xn = *(const float4*)(XT + (size_t)((ch+1)*128 + kk)*256 + r0 + seg*4);
            cp_wait1();
        } else {
            cp_wait0();
        }
        __syncthreads();

        const ull*   xb = Xc + (ks*16)*16 + 2*rp;
        const float* wb = Wc + (ks*16)*32 + qc*4;
        #pragma unroll 4
        for (int k2 = 0; k2 < 16; k2++){
            ulonglong2 xd = *(const ulonglong2*)(xb + k2*16);
            ulonglong2 wv = *(const ulonglong2*)(wb + k2*32);
            aA0 = fma2_(wv.x, xd.x, aA0);
            aA1 = fma2_(wv.y, xd.x, aA1);
            aB0 = fma2_(wv.x, xd.y, aB0);
            aB1 = fma2_(wv.y, xd.y, aB1);
        }
        __syncthreads();

        if (ch + 1 < NCH){
            ull* dst = Xd + ((ch+1)&1)*XD_ULL + kk*16 + seg*4;
            ulonglong2 d0, d1;
            d0.x = pack2_(xn.x, xn.x); d0.y = pack2_(xn.y, xn.y);
            d1.x = pack2_(xn.z, xn.z); d1.y = pack2_(xn.w, xn.w);
            *(ulonglong2*)dst = d0;
            *(ulonglong2*)(dst+2) = d1;
        }
    }

    // ---- k-split reduction through smem (PART aliases Xd buffer 0: last
    // compute chunk read buffer 1 for NCH in {2,6}; sync above covers reuse)
    ull* PART = Xd;
    {
        ull* dst = PART + (((ks<<6) + (t & 63))<<2);
        ulonglong2 p0, p1;
        p0.x = aA0; p0.y = aA1;
        p1.x = aB0; p1.y = aB1;
        *(ulonglong2*)dst = p0;
        *(ulonglong2*)(dst+2) = p1;
    }
    __syncthreads();

    if (t < 64){
        int pos = t, prp = pos & 7, pqc = pos >> 3;
        float2 e01 = make_float2(0.f,0.f), e23 = e01, o01 = e01, o23 = e01;
        #pragma unroll
        for (int s = 0; s < 8; s++){
            const ull* e = PART + (((s<<6) + pos)<<2);
            ulonglong2 u0 = *(const ulonglong2*)e;
            ulonglong2 u1 = *(const ulonglong2*)(e+2);
            float2 f;
            f = unpack2_(u0.x); e01.x += f.x; e01.y += f.y;
            f = unpack2_(u0.y); e23.x += f.x; e23.y += f.y;
            f = unpack2_(u1.x); o01.x += f.x; o01.y += f.y;
            f = unpack2_(u1.y); o23.x += f.x; o23.y += f.y;
        }
        float4 bb = *(const float4*)(bias + c0 + pqc*4);
        float ve0 = fmaxf(e01.x + bb.x, 0.f), ve1 = fmaxf(e01.y + bb.y, 0.f);
        float ve2 = fmaxf(e23.x + bb.z, 0.f), ve3 = fmaxf(e23.y + bb.w, 0.f);
        float vo0 = fmaxf(o01.x + bb.x, 0.f), vo1 = fmaxf(o01.y + bb.y, 0.f);
        float vo2 = fmaxf(o23.x + bb.z, 0.f), vo3 = fmaxf(o23.y + bb.w, 0.f);
        int re = r0 + 2*prp, cA = c0 + pqc*4;
        if (WRITE_T){
            *(float2*)(Out + (size_t)(cA+0)*256 + re) = make_float2(ve0, vo0);
            *(float2*)(Out + (size_t)(cA+1)*256 + re) = make_float2(ve1, vo1);
            *(float2*)(Out + (size_t)(cA+2)*256 + re) = make_float2(ve2, vo2);
            *(float2*)(Out + (size_t)(cA+3)*256 + re) = make_float2(ve3, vo3);
        } else {
            *(float4*)(Out + (size_t)re*256 + cA)     = make_float4(ve0, ve1, ve2, ve3);
            *(float4*)(Out + (size_t)(re+1)*256 + cA) = make_float4(vo0, vo1, vo2, vo3);
        }
    }
    __syncthreads();
}

// ============================================================
// Kernel 2: fused fill | GEMM1 | GB | GEMM2 | GB | heads | sample_ln
// grid 128 x 512 threads. dynamic smem = 65536 B.
// ============================================================
#define FUSED_SMEM_BYTES 65536

__global__ void __launch_bounds__(512, 1)
fused_kernel(const float* __restrict__ W1, const float* __restrict__ b1,
             const float* __restrict__ W2, const float* __restrict__ b2,
             const float* __restrict__ Wn, const float* __restrict__ bn,
             const float* __restrict__ Woff, const float* __restrict__ boff,
             const float* __restrict__ Ww, const float* __restrict__ bw,
             const float* __restrict__ feats,
             const float* __restrict__ gamma, const float* __restrict__ beta,
             float* __restrict__ out, int write_next)
{
    extern __shared__ ull smu[];
    ull*   Xd = smu;                        // 2 * 2048 ull
    float* Wf = (float*)(smu + 2*XD_ULL);   // 2 * 4096 floats

    __shared__ float  Hs2[2][256];
    __shared__ float  HWn[768], HWo[192], HWw[128];
    __shared__ float  HD2[2][28];
    __shared__ float  SPx[2][4], SPy[2][4], SPz[2][4], SPw[2][4];
    __shared__ int    cq2[2][40];
    __shared__ float  cw2[2][40];
    __shared__ int    nq2[2];
    __shared__ float2 sred2[2][8];
    __shared__ float  s_mu[2], s_rstd[2];

    int t = threadIdx.x;
    int b = blockIdx.x;

    // ---- phase 0: beta fill (skips sampled positions)
    {
        float4* out4 = (float4*)out;
        const unsigned tm = 0x5Au;
        const unsigned hm = (1u<<4)|(1u<<12)|(1u<<19)|(1u<<27);
        #pragma unroll
        for (int u = 0; u < 8; u++){
            int f = b*4096 + u*512 + t;
            int c = f >> 13;
            int p = f & 8191;
            int t3 = p >> 10, h3 = (p >> 5) & 31, w3 = p & 31;
            bool samp = ((tm >> t3) & 1u) && ((hm >> h3) & 1u) && ((hm >> w3) & 1u);
            if (!samp){
                float bb = __ldg(&beta[c]);
                out4[f] = make_float4(bb, bb, bb, bb);
            }
        }
    }

    // ---- phase 1: GEMM1 (K=768) -> g_H1T
    gemm_phase<6, true>(g_XT, W1, b1, g_H1T, Xd, Wf);
    global_bar(0);

    // ---- phase 2: GEMM2 (K=256) -> g_H2
    gemm_phase<2, false>(g_H1T, W2, b2, g_H2, Xd, Wf);
    global_bar(1);

    // ---- phase 3: heads + dedup, both rows concurrently
    int row = t >> 8;
    int u   = t & 255;
    int rr  = b*2 + row;
    int p   = flat_idx(rr & 63);

    Hs2[row][u] = g_H2[(size_t)rr*256 + u];
    for (int k = t; k < 768; k += 512) HWn[k] = Wn[k];
    if (t < 192) HWo[t] = Woff[t];
    if (t >= 256 && t < 384) HWw[t-256] = Ww[t-256];
    __syncthreads();

    if (u < 3){
        float s = bn[u];
        #pragma unroll 8
        for (int k = 0; k < 256; k++) s = fmaf(Hs2[row][k], HWn[k*3 + u], s);
        HD2[row][u] = s;
    } else if (u >= 8 && u < 20){
        int v = u - 8;
        int no = v / 3, jo = v - no*3;
        float s = boff[jo];
        #pragma unroll 8
        for (int dd = 0; dd < 64; dd++) s = fmaf(Hs2[row][no*64+dd], HWo[dd*3 + jo], s);
        HD2[row][8+v] = s;
    } else if (u >= 20 && u < 28){
        int v = u - 20;
        int no = v >> 1, comp = v & 1;
        float s = bw[comp];
        #pragma unroll 8
        for (int dd = 0; dd < 64; dd++) s = fmaf(Hs2[row][no*64+dd], HWw[dd*2 + comp], s);
        HD2[row][20+v] = s;
    }
    __syncthreads();

    if (u == 0){
        int tq = p >> 10, hq = (p >> 5) & 31, wq = p & 31;
        float tn = (float)tq * (1.0f/7.0f);
        float hn = (float)hq * (1.0f/31.0f);
        float wn = (float)wq * (1.0f/31.0f);
        float ivt = invsigf_(tn), ivh = invsigf_(hn), ivw = invsigf_(wn);

        #pragma unroll
        for (int no = 0; no < 4; no++){
            float o0 = HD2[row][8+no*3+0], o1 = HD2[row][8+no*3+1], o2 = HD2[row][8+no*3+2];
            float st = sigmoidf_(ivt + o0)*2.0f - 1.0f;
            float sh = sigmoidf_(ivh + o1)*2.0f - 1.0f;
            float sw = sigmoidf_(ivw + o2)*2.0f - 1.0f;
            SPx[row][no] = ((st + 1.0f)*32.0f - 1.0f)*0.5f;
            SPy[row][no] = ((sh + 1.0f)*32.0f - 1.0f)*0.5f;
            SPz[row][no] = ((sw + 1.0f)*8.0f  - 1.0f)*0.5f;
            float za = HD2[row][20+no*2], zb = HD2[row][21+no*2];
            SPw[row][no] = 1.0f/(1.0f + expf(za - zb));
        }

        if (write_next){
            float d0 = sigmoidf_(ivt + HD2[row][0]) * 7.0f;
            float d1 = sigmoidf_(ivh + HD2[row][1]) * 31.0f;
            float d2 = sigmoidf_(ivw + HD2[row][2]) * 31.0f;
            int ni = 1024*(int)rintf(d0) + 32*(int)rintf(d1) + (int)rintf(d2);
            out[FEAT_OUT_ELEMS + rr] = (float)ni;
        }
    }
    __syncthreads();

    if (u < 32){
        const unsigned full = 0xffffffffu;
        int lane = t & 31;
        int no = lane >> 3, jj = lane & 7;
        float ix = SPx[row][no], iy = SPy[row][no], iz = SPz[row][no];
        float wo = SPw[row][no];
        float x0f = floorf(ix), y0f = floorf(iy), z0f = floorf(iz);
        int dx = jj & 1, dy = (jj >> 1) & 1, dz = jj >> 2;
        int xi = (int)x0f + dx, yi = (int)y0f + dy, zi = (int)z0f + dz;
        float fx = ix - x0f, fy = iy - y0f, fz = iz - z0f;
        float w = (dx ? fx : 1.0f-fx) * (dy ? fy : 1.0f-fy) * (dz ? fz : 1.0f-fz) * wo;
        bool valid = (xi >= 0) & (xi < W_) & (yi >= 0) & (yi < H_) & (zi >= 0) & (zi < T_);
        if (!valid) w = 0.0f;
        int q = (min(max(zi,0),T_-1)*H_ + min(max(yi,0),H_-1))*W_ + min(max(xi,0),W_-1);

        unsigned mask = __match_any_sync(full, q);
        float wsum = 0.0f;
        #pragma unroll
        for (int s2 = 0; s2 < 32; s2++){
            float wv = __shfl_sync(full, w, s2);
            int   qv = __shfl_sync(full, q, s2);
            if (qv == q) wsum += wv;
        }
        int leader = __ffs(mask) - 1;
        bool is_leader = (lane == leader);
        unsigned bal = __ballot_sync(full, is_leader);
        int pos = __popc(bal & ((1u << lane) - 1u));
        if (is_leader){ cq2[row][pos] = q; cw2[row][pos] = wsum; }
        __syncwarp();
        if (lane == 0){
            int nq = __popc(bal);
            bool found = false;
            for (int j2 = 0; j2 < nq; j2++){
                if (cq2[row][j2] == p){ cw2[row][j2] += 1.0f; found = true; break; }
            }
            if (!found){ cq2[row][nq] = p; cw2[row][nq] = 1.0f; nq++; }
            nq2[row] = nq;
        }
    }
    __syncthreads();

    // ---- phase 4: sample + LN, both rows concurrently
    {
        int l  = rr >> 6;
        int c  = u;
        int nq = nq2[row];
        const float* fb = feats + (size_t)c*(THW_*L_) + l;
        float acc = 0.0f;
        #pragma unroll 4
        for (int j2 = 0; j2 < nq; j2++)
            acc = fmaf(cw2[row][j2], __ldg(fb + (size_t)cq2[row][j2]*L_), acc);
        float v = acc;

        const unsigned full = 0xffffffffu;
        float sx = v, sy = v*v;
        #pragma unroll
        for (int o = 16; o > 0; o >>= 1){
            sx += __shfl_xor_sync(full, sx, o);
            sy += __shfl_xor_sync(full, sy, o);
        }
        int lane = t & 31;
        int wrp  = (t >> 5) & 7;
        if (lane == 0) sred2[row][wrp] = make_float2(sx, sy);
        __syncthreads();
        if (u == 0){
            float mx = 0.f, my = 0.f;
            #pragma unroll
            for (int k = 0; k < 8; k++){ mx += sred2[row][k].x; my += sred2[row][k].y; }
            float mu  = mx * (1.0f/256.0f);
            float var = my * (1.0f/256.0f) - mu*mu;
            s_mu[row] = mu;
            s_rstd[row] = rsqrtf(var + 1e-5f);
        }
        __syncthreads();

        float o = (v - s_mu[row]) * s_rstd[row] * __ldg(&gamma[c]) + __ldg(&beta[c]);
        out[((size_t)c*THW_ + p)*L_ + l] = o;
    }
}

// ============================================================
extern "C" void kernel_launch(void* const* d_in, const int* in_sizes, int n_in,
                              void* d_out, int out_size)
{
    const float* feats = (const float*)d_in[0];
    const float* pos   = (const float*)d_in[1];
    const float* W1    = (const float*)d_in[2];
    const float* b1    = (const float*)d_in[3];
    const float* W2    = (const float*)d_in[4];
    const float* b2    = (const float*)d_in[5];
    const float* Wn    = (const float*)d_in[6];
    const float* bn    = (const float*)d_in[7];
    // d_in[8]=Wl, d_in[9]=bl dead (softmax row-sum == 1; LN scale-invariant)
    const float* Woff  = (const float*)d_in[10];
    const float* boff  = (const float*)d_in[11];
    const float* Ww    = (const float*)d_in[12];
    const float* bw    = (const float*)d_in[13];
    const float* gamma = (const float*)d_in[14];
    const float* beta  = (const float*)d_in[15];
    float* out = (float*)d_out;

    int write_next = (out_size >= FEAT_OUT_ELEMS + NROWS) ? 1 : 0;

    static int smem_set = 0;
    if (!smem_set){
        cudaFuncSetAttribute(fused_kernel, cudaFuncAttributeMaxDynamicSharedMemorySize,
                             FUSED_SMEM_BYTES);
        smem_set = 1;
    }

    prep_kernel<<<256, 512>>>(feats, pos);
    fused_kernel<<<NB, 512, FUSED_SMEM_BYTES>>>(W1, b1, W2, b2, Wn, bn, Woff, boff,
                                                Ww, bw, feats, gamma, beta, out, write_next);
}

// round 11
// speedup vs baseline: 1.4312x; 1.0211x over previous
#include <cuda_runtime.h>
#include <math.h>

#define C_    256
#define T_    8
#define H_    32
#define W_    32
#define L_    4
#define THW_  8192
#define NROWS 256
#define FEAT_OUT_ELEMS (C_*THW_*L_)   // 2097152
#define NB 128
#define NBG 8                          // blocks per barrier group

// ---- scratch (device globals; no allocation) ----
__device__ float    g_XT [768*256];    // X transposed: [k][row]
__device__ float    g_H1T[256*256];    // H1 transposed: [k][row]
__device__ float    g_H2 [256*256];    // H2 row-major: [row][c]
__device__ unsigned g_barrier[1];          // global bar (monotonic, replay-safe)
__device__ unsigned g_gbar[2][16*64];      // group bars, 256B apart

__constant__ int c_tt[4] = {1,3,4,6};
__constant__ int c_hh[4] = {4,12,19,27};

__device__ __forceinline__ int flat_idx(int n){
    int it = n >> 4, ih = (n >> 2) & 3, iw = n & 3;
    return (c_tt[it]*H_ + c_hh[ih])*W_ + c_hh[iw];
}
__device__ __forceinline__ float sigmoidf_(float x){ return 1.0f/(1.0f+expf(-x)); }
__device__ __forceinline__ float invsigf_(float x){
    return logf(fmaxf(x,1e-5f)/fmaxf(1.0f-x,1e-5f));
}
__device__ __forceinline__ void cp_async16(void* smem_dst, const void* gmem_src){
    unsigned s = (unsigned)__cvta_generic_to_shared(smem_dst);
    asm volatile("cp.async.cg.shared.global [%0], [%1], 16;\n" :: "r"(s), "l"(gmem_src));
}
__device__ __forceinline__ void cp_commit(){ asm volatile("cp.async.commit_group;\n"); }
__device__ __forceinline__ void cp_wait0(){ asm volatile("cp.async.wait_group 0;\n"); }
__device__ __forceinline__ void cp_wait1(){ asm volatile("cp.async.wait_group 1;\n"); }

typedef unsigned long long ull;
__device__ __forceinline__ ull fma2_(ull a, ull b, ull c){
    ull d; asm("fma.rn.f32x2 %0, %1, %2, %3;" : "=l"(d) : "l"(a), "l"(b), "l"(c)); return d;
}
__device__ __forceinline__ ull pack2_(float x, float y){
    ull r; asm("mov.b64 %0, {%1, %2};" : "=l"(r) : "f"(x), "f"(y)); return r;
}
__device__ __forceinline__ float2 unpack2_(ull v){
    float2 r; asm("mov.b64 {%0, %1}, %2;" : "=f"(r.x), "=f"(r.y) : "l"(v)); return r;
}

// Global device barrier (all NB blocks). Monotonic, replay-safe.
__device__ __forceinline__ void global_bar(){
    __syncthreads();
    if (threadIdx.x == 0){
        __threadfence();
        unsigned old  = atomicAdd(&g_barrier[0], 1u);
        unsigned goal = old - (old % (unsigned)NB) + (unsigned)NB;
        volatile unsigned* p = &g_barrier[0];
        while ((int)(*p - goal) < 0){}
        __threadfence();
    }
    __syncthreads();
}
// Group barrier: only the NBG blocks sharing g = blockIdx.x>>3.
__device__ __forceinline__ void group_bar(int id, int g){
    __syncthreads();
    if (threadIdx.x == 0){
        __threadfence();
        unsigned* cnt = &g_gbar[id][g*64];
        unsigned old  = atomicAdd(cnt, 1u);
        unsigned goal = old - (old % (unsigned)NBG) + (unsigned)NBG;
        volatile unsigned* p = cnt;
        while ((int)(*p - goal) < 0){}
        __threadfence();
    }
    __syncthreads();
}

// ============================================================
// GEMM phase (register-tiled): Out = relu(X[256,K] @ W[K,256] + bias)
// X k-major. tile 16r x 32c; thread = (rp, qc, ks). 8 MACs / 2 LDS.128.
// ============================================================
#define XD_ULL 2048
#define WF_F   4096

__device__ __forceinline__ void prime_W(const float* __restrict__ Wg, float* Wf,
                                        int c0, int t){
    #pragma unroll
    for (int u = 0; u < 2; u++){
        int idx4 = t + u*512;
        int wk = idx4 >> 3, ws = idx4 & 7;
        cp_async16(Wf + wk*32 + ws*4, Wg + (size_t)wk*256 + c0 + ws*4);
    }
    cp_commit();
}

template<int NCH, bool WRITE_T>
__device__ __forceinline__ void gemm_phase(
    const float* __restrict__ XT, const float* __restrict__ Wg,
    const float* __restrict__ bias, float* __restrict__ Out,
    ull* Xd, float* Wf)
{
    int t  = threadIdx.x;
    int c0 = (blockIdx.x & 7) * 32;
    int r0 = (blockIdx.x >> 3) * 16;
    int rp = t & 7, qc = (t >> 3) & 7, ks = t >> 6;
    int kk = t >> 2, seg = t & 3;

    // X prime chunk 0 (W chunk 0 was primed by caller)
    {
        float4 xv = *(const float4*)(XT + (size_t)kk*256 + r0 + seg*4);
        ull* dst = Xd + kk*16 + seg*4;
        ulonglong2 d0, d1;
        d0.x = pack2_(xv.x, xv.x); d0.y = pack2_(xv.y, xv.y);
        d1.x = pack2_(xv.z, xv.z); d1.y = pack2_(xv.w, xv.w);
        *(ulonglong2*)dst = d0;
        *(ulonglong2*)(dst+2) = d1;
    }

    ull aA0=0ULL, aA1=0ULL, aB0=0ULL, aB1=0ULL;
    float4 xn;

    #pragma unroll 1
    for (int ch = 0; ch < NCH; ch++){
        ull*   Xc = Xd + (ch & 1)*XD_ULL;
        float* Wc = Wf + (ch & 1)*WF_F;
        if (ch + 1 < NCH){
            float* Wn2 = Wf + ((ch+1)&1)*WF_F;
            #pragma unroll
            for (int u = 0; u < 2; u++){
                int idx4 = t + u*512;
                int wk = idx4 >> 3, ws = idx4 & 7;
                cp_async16(Wn2 + wk*32 + ws*4,
                           Wg + (size_t)((ch+1)*128 + wk)*256 + c0 + ws*4);
            }
            cp_commit();
            xn = *(const float4*)(XT + (size_t)((ch+1)*128 + kk)*256 + r0 + seg*4);
            cp_wait1();
        } else {
            cp_wait0();
        }
        __syncthreads();

        const ull*   xb = Xc + (ks*16)*16 + 2*rp;
        const float* wb = Wc + (ks*16)*32 + qc*4;
        #pragma unroll 4
        for (int k2 = 0; k2 < 16; k2++){
            ulonglong2 xd = *(const ulonglong2*)(xb + k2*16);
            ulonglong2 wv = *(const ulonglong2*)(wb + k2*32);
            aA0 = fma2_(wv.x, xd.x, aA0);
            aA1 = fma2_(wv.y, xd.x, aA1);
            aB0 = fma2_(wv.x, xd.y, aB0);
            aB1 = fma2_(wv.y, xd.y, aB1);
        }
        __syncthreads();

        if (ch + 1 < NCH){
            ull* dst = Xd + ((ch+1)&1)*XD_ULL + kk*16 + seg*4;
            ulonglong2 d0, d1;
            d0.x = pack2_(xn.x, xn.x); d0.y = pack2_(xn.y, xn.y);
            d1.x = pack2_(xn.z, xn.z); d1.y = pack2_(xn.w, xn.w);
            *(ulonglong2*)dst = d0;
            *(ulonglong2*)(dst+2) = d1;
        }
    }

    // k-split reduction through smem (PART aliases Xd buffer 0; last chunk
    // computed from buffer 1 for NCH in {2,6}; sync above covers reuse)
    ull* PART = Xd;
    {
        ull* dst = PART + (((ks<<6) + (t & 63))<<2);
        ulonglong2 p0, p1;
        p0.x = aA0; p0.y = aA1;
        p1.x = aB0; p1.y = aB1;
        *(ulonglong2*)dst = p0;
        *(ulonglong2*)(dst+2) = p1;
    }
    __syncthreads();

    if (t < 64){
        int pos = t, prp = pos & 7, pqc = pos >> 3;
        float2 e01 = make_float2(0.f,0.f), e23 = e01, o01 = e01, o23 = e01;
        #pragma unroll
        for (int s = 0; s < 8; s++){
            const ull* e = PART + (((s<<6) + pos)<<2);
            ulonglong2 u0 = *(const ulonglong2*)e;
            ulonglong2 u1 = *(const ulonglong2*)(e+2);
            float2 f;
            f = unpack2_(u0.x); e01.x += f.x; e01.y += f.y;
            f = unpack2_(u0.y); e23.x += f.x; e23.y += f.y;
            f = unpack2_(u1.x); o01.x += f.x; o01.y += f.y;
            f = unpack2_(u1.y); o23.x += f.x; o23.y += f.y;
        }
        float4 bb = *(const float4*)(bias + c0 + pqc*4);
        float ve0 = fmaxf(e01.x + bb.x, 0.f), ve1 = fmaxf(e01.y + bb.y, 0.f);
        float ve2 = fmaxf(e23.x + bb.z, 0.f), ve3 = fmaxf(e23.y + bb.w, 0.f);
        float vo0 = fmaxf(o01.x + bb.x, 0.f), vo1 = fmaxf(o01.y + bb.y, 0.f);
        float vo2 = fmaxf(o23.x + bb.z, 0.f), vo3 = fmaxf(o23.y + bb.w, 0.f);
        int re = r0 + 2*prp, cA = c0 + pqc*4;
        if (WRITE_T){
            *(float2*)(Out + (size_t)(cA+0)*256 + re) = make_float2(ve0, vo0);
            *(float2*)(Out + (size_t)(cA+1)*256 + re) = make_float2(ve1, vo1);
            *(float2*)(Out + (size_t)(cA+2)*256 + re) = make_float2(ve2, vo2);
            *(float2*)(Out + (size_t)(cA+3)*256 + re) = make_float2(ve3, vo3);
        } else {
            *(float4*)(Out + (size_t)re*256 + cA)     = make_float4(ve0, ve1, ve2, ve3);
            *(float4*)(Out + (size_t)(re+1)*256 + cA) = make_float4(vo0, vo1, vo2, vo3);
        }
    }
    __syncthreads();
}

// ============================================================
// ONE kernel: prep | fill | GBAR | GEMM1 | grp | GEMM2 | grp | tail
// grid 128 x 512 threads. dynamic smem = 65536 B.
// ============================================================
#define FUSED_SMEM_BYTES 65536

__global__ void __launch_bounds__(512, 1)
fused_kernel(const float* __restrict__ feats, const float* __restrict__ pos,
             const float* __restrict__ W1, const float* __restrict__ b1,
             const float* __restrict__ W2, const float* __restrict__ b2,
             const float* __restrict__ Wn, const float* __restrict__ bn,
             const float* __restrict__ Woff, const float* __restrict__ boff,
             const float* __restrict__ Ww, const float* __restrict__ bw,
             const float* __restrict__ gamma, const float* __restrict__ beta,
             float* __restrict__ out, int write_next)
{
    extern __shared__ ull smu[];
    ull*   Xd = smu;                        // 2 * 2048 ull
    float* Wf = (float*)(smu + 2*XD_ULL);   // 2 * 4096 floats

    __shared__ float  Hs2[2][256];
    __shared__ float  HWn[768], HWo[192], HWw[128];
    __shared__ float  HD2[2][28];
    __shared__ float  SPx[2][4], SPy[2][4], SPz[2][4], SPw[2][4];
    __shared__ int    cq2[2][40];
    __shared__ float  cw2[2][40];
    __shared__ int    nq2[2];
    __shared__ float2 sred2[2][8];
    __shared__ float  s_mu[2], s_rstd[2];

    int t = threadIdx.x;
    int b = blockIdx.x;
    int g = b >> 3;
    int c0 = (b & 7) * 32;

    // ---- W1 chunk-0 prefetch: overlaps all of prep+fill
    prime_W(W1, Wf, c0, t);

    // ---- phase A: prep. Block handles channels 2b (half 0) and 2b+1 (half 1).
    {
        int half = t >> 8;
        int tt   = t & 255;
        int c    = 2*b + half;
        const float4* f4 = reinterpret_cast<const float4*>(feats + (size_t)c*(THW_*L_));
        float4 s = make_float4(0.f,0.f,0.f,0.f);
        #pragma unroll 4
        for (int j = 0; j < 32; j++){
            float4 v = f4[tt + j*256];
            s.x += v.x; s.y += v.y; s.z += v.z; s.w += v.w;
        }
        float4* sm4 = (float4*)smu;   // overlays Xd; prep ends before GEMM
        // note: Wf (cp.async dest) is beyond sm4[512] region — no overlap
        float4* sm4h = sm4 + (half<<8);
        sm4h[tt] = s;
        __syncthreads();
        for (int o = 128; o > 0; o >>= 1){
            if (tt < o){
                float4 a = sm4h[tt], bb = sm4h[tt+o];
                sm4h[tt] = make_float4(a.x+bb.x, a.y+bb.y, a.z+bb.z, a.w+bb.w);
            }
            __syncthreads();
        }
        float4 mean = sm4h[0];
        const float inv = 1.0f/8192.0f;
        int row = tt;
        int l = row >> 6;
        int p = flat_idx(row & 63);
        float fv = feats[((size_t)c*THW_ + p)*L_ + l];
        float pv = pos  [((size_t)c*THW_ + p)*L_ + l];
        float gv = (l==0 ? mean.x : l==1 ? mean.y : l==2 ? mean.z : mean.w) * inv;
        g_XT[(size_t)c*256 + row]       = fv;
        g_XT[(size_t)(256+c)*256 + row] = pv;
        g_XT[(size_t)(512+c)*256 + row] = gv;
    }

    // ---- phase B: beta fill (skips sampled positions) — overlaps barrier skew
    {
        float4* out4 = (float4*)out;
        const unsigned tm = 0x5Au;
        const unsigned hm = (1u<<4)|(1u<<12)|(1u<<19)|(1u<<27);
        #pragma unroll
        for (int u = 0; u < 8; u++){
            int f = b*4096 + u*512 + t;
            int c = f >> 13;
            int p = f & 8191;
            int t3 = p >> 10, h3 = (p >> 5) & 31, w3 = p & 31;
            bool samp = ((tm >> t3) & 1u) && ((hm >> h3) & 1u) && ((hm >> w3) & 1u);
            if (!samp){
                float bb = __ldg(&beta[c]);
                out4[f] = make_float4(bb, bb, bb, bb);
            }
        }
    }

    global_bar();                       // XT complete chip-wide

    // ---- phase C: GEMM1 (K=768) -> g_H1T
    gemm_phase<6, true>(g_XT, W1, b1, g_H1T, Xd, Wf);

    prime_W(W2, Wf, c0, t);             // W2 chunk 0 overlaps group barrier
    group_bar(0, g);                    // H1T rows of this group complete

    // ---- phase D: GEMM2 (K=256) -> g_H2
    gemm_phase<2, false>(g_H1T, W2, b2, g_H2, Xd, Wf);
    group_bar(1, g);                    // H2 rows of this group complete

    // ---- phase E: heads + dedup, rows 2b / 2b+1
    int row = t >> 8;
    int u   = t & 255;
    int rr  = b*2 + row;
    int p   = flat_idx(rr & 63);

    Hs2[row][u] = g_H2[(size_t)rr*256 + u];
    for (int k = t; k < 768; k += 512) HWn[k] = Wn[k];
    if (t < 192) HWo[t] = Woff[t];
    if (t >= 256 && t < 384) HWw[t-256] = Ww[t-256];
    __syncthreads();

    if (u < 3){
        float s = bn[u];
        #pragma unroll 8
        for (int k = 0; k < 256; k++) s = fmaf(Hs2[row][k], HWn[k*3 + u], s);
        HD2[row][u] = s;
    } else if (u >= 8 && u < 20){
        int v = u - 8;
        int no = v / 3, jo = v - no*3;
        float s = boff[jo];
        #pragma unroll 8
        for (int dd = 0; dd < 64; dd++) s = fmaf(Hs2[row][no*64+dd], HWo[dd*3 + jo], s);
        HD2[row][8+v] = s;
    } else if (u >= 20 && u < 28){
        int v = u - 20;
        int no = v >> 1, comp = v & 1;
        float s = bw[comp];
        #pragma unroll 8
        for (int dd = 0; dd < 64; dd++) s = fmaf(Hs2[row][no*64+dd], HWw[dd*2 + comp], s);
        HD2[row][20+v] = s;
    }
    __syncthreads();

    if (u == 0){
        int tq = p >> 10, hq = (p >> 5) & 31, wq = p & 31;
        float tn = (float)tq * (1.0f/7.0f);
        float hn = (float)hq * (1.0f/31.0f);
        float wn = (float)wq * (1.0f/31.0f);
        float ivt = invsigf_(tn), ivh = invsigf_(hn), ivw = invsigf_(wn);

        #pragma unroll
        for (int no = 0; no < 4; no++){
            float o0 = HD2[row][8+no*3+0], o1 = HD2[row][8+no*3+1], o2 = HD2[row][8+no*3+2];
            float st = sigmoidf_(ivt + o0)*2.0f - 1.0f;
            float sh = sigmoidf_(ivh + o1)*2.0f - 1.0f;
            float sw = sigmoidf_(ivw + o2)*2.0f - 1.0f;
            SPx[row][no] = ((st + 1.0f)*32.0f - 1.0f)*0.5f;
            SPy[row][no] = ((sh + 1.0f)*32.0f - 1.0f)*0.5f;
            SPz[row][no] = ((sw + 1.0f)*8.0f  - 1.0f)*0.5f;
            float za = HD2[row][20+no*2], zb = HD2[row][21+no*2];
            SPw[row][no] = 1.0f/(1.0f + expf(za - zb));
        }

        if (write_next){
            float d0 = sigmoidf_(ivt + HD2[row][0]) * 7.0f;
            float d1 = sigmoidf_(ivh + HD2[row][1]) * 31.0f;
            float d2 = sigmoidf_(ivw + HD2[row][2]) * 31.0f;
            int ni = 1024*(int)rintf(d0) + 32*(int)rintf(d1) + (int)rintf(d2);
            out[FEAT_OUT_ELEMS + rr] = (float)ni;
        }
    }
    __syncthreads();

    if (u < 32){   // warp 0 (row 0) and warp 8 (row 1)
        const unsigned full = 0xffffffffu;
        int lane = t & 31;
        int no = lane >> 3, jj = lane & 7;
        float ix = SPx[row][no], iy = SPy[row][no], iz = SPz[row][no];
        float wo = SPw[row][no];
        float x0f = floorf(ix), y0f = floorf(iy), z0f = floorf(iz);
        int dx = jj & 1, dy = (jj >> 1) & 1, dz = jj >> 2;
        int xi = (int)x0f + dx, yi = (int)y0f + dy, zi = (int)z0f + dz;
        float fx = ix - x0f, fy = iy - y0f, fz = iz - z0f;
        float w = (dx ? fx : 1.0f-fx) * (dy ? fy : 1.0f-fy) * (dz ? fz : 1.0f-fz) * wo;
        bool valid = (xi >= 0) & (xi < W_) & (yi >= 0) & (yi < H_) & (zi >= 0) & (zi < T_);
        if (!valid) w = 0.0f;
        int q = (min(max(zi,0),T_-1)*H_ + min(max(yi,0),H_-1))*W_ + min(max(xi,0),W_-1);

        unsigned mask = __match_any_sync(full, q);
        float wsum = 0.0f;
        #pragma unroll
        for (int s2 = 0; s2 < 32; s2++){
            float wv = __shfl_sync(full, w, s2);
            int   qv = __shfl_sync(full, q, s2);
            if (qv == q) wsum += wv;
        }
        int leader = __ffs(mask) - 1;
        bool is_leader = (lane == leader);
        unsigned bal = __ballot_sync(full, is_leader);
        int pos = __popc(bal & ((1u << lane) - 1u));
        if (is_leader){ cq2[row][pos] = q; cw2[row][pos] = wsum; }
        __syncwarp();
        if (lane == 0){
            int nq = __popc(bal);
            bool found = false;
            for (int j2 = 0; j2 < nq; j2++){
                if (cq2[row][j2] == p){ cw2[row][j2] += 1.0f; found = true; break; }
            }
            if (!found){ cq2[row][nq] = p; cw2[row][nq] = 1.0f; nq++; }
            nq2[row] = nq;
        }
    }
    __syncthreads();

    // ---- phase F: sample + LN
    {
        int l  = rr >> 6;
        int c  = u;
        int nq = nq2[row];
        const float* fb = feats + (size_t)c*(THW_*L_) + l;
        float acc = 0.0f;
        #pragma unroll 4
        for (int j2 = 0; j2 < nq; j2++)
            acc = fmaf(cw2[row][j2], __ldg(fb + (size_t)cq2[row][j2]*L_), acc);
        float v = acc;

        const unsigned full = 0xffffffffu;
        float sx = v, sy = v*v;
        #pragma unroll
        for (int o = 16; o > 0; o >>= 1){
            sx += __shfl_xor_sync(full, sx, o);
            sy += __shfl_xor_sync(full, sy, o);
        }
        int lane = t & 31;
        int wrp  = (t >> 5) & 7;
        if (lane == 0) sred2[row][wrp] = make_float2(sx, sy);
        __syncthreads();
        if (u == 0){
            float mx = 0.f, my = 0.f;
            #pragma unroll
            for (int k = 0; k < 8; k++){ mx += sred2[row][k].x; my += sred2[row][k].y; }
            float mu  = mx * (1.0f/256.0f);
            float var = my * (1.0f/256.0f) - mu*mu;
            s_mu[row] = mu;
            s_rstd[row] = rsqrtf(var + 1e-5f);
        }
        __syncthreads();

        float o = (v - s_mu[row]) * s_rstd[row] * __ldg(&gamma[c]) + __ldg(&beta[c]);
        out[((size_t)c*THW_ + p)*L_ + l] = o;
    }
}

// ============================================================
extern "C" void kernel_launch(void* const* d_in, const int* in_sizes, int n_in,
                              void* d_out, int out_size)
{
    const float* feats = (const float*)d_in[0];
    const float* pos   = (const float*)d_in[1];
    const float* W1    = (const float*)d_in[2];
    const float* b1    = (const float*)d_in[3];
    const float* W2    = (const float*)d_in[4];
    const float* b2    = (const float*)d_in[5];
    const float* Wn    = (const float*)d_in[6];
    const float* bn    = (const float*)d_in[7];
    // d_in[8]=Wl, d_in[9]=bl dead (softmax row-sum == 1; LN scale-invariant)
    const float* Woff  = (const float*)d_in[10];
    const float* boff  = (const float*)d_in[11];
    const float* Ww    = (const float*)d_in[12];
    const float* bw    = (const float*)d_in[13];
    const float* gamma = (const float*)d_in[14];
    const float* beta  = (const float*)d_in[15];
    float* out = (float*)d_out;

    int write_next = (out_size >= FEAT_OUT_ELEMS + NROWS) ? 1 : 0;

    static int smem_set = 0;
    if (!smem_set){
        cudaFuncSetAttribute(fused_kernel, cudaFuncAttributeMaxDynamicSharedMemorySize,
                             FUSED_SMEM_BYTES);
        smem_set = 1;
    }

    fused_kernel<<<NB, 512, FUSED_SMEM_BYTES>>>(feats, pos, W1, b1, W2, b2, Wn, bn,
                                                Woff, boff, Ww, bw, gamma, beta,
                                                out, write_next);
}

// round 12
// speedup vs baseline: 1.5000x; 1.0481x over previous
#include <cuda_runtime.h>
#include <math.h>

#define C_    256
#define T_    8
#define H_    32
#define W_    32
#define L_    4
#define THW_  8192
#define NROWS 256
#define FEAT_OUT_ELEMS (C_*THW_*L_)   // 2097152
#define NB 128
#define NBG 8

// ---- scratch (device globals; no allocation) ----
__device__ float    g_XT [512*256];    // X transposed (feat|pos only): [k][row]
__device__ float    g_H1T[256*256];    // H1 transposed: [k][row]
__device__ float    g_H2 [256*256];    // H2 row-major
__device__ float    g_glob[4*256];     // per-l channel means
__device__ unsigned g_barrier[1];
__device__ unsigned g_gbar[2][16*64];

__constant__ int c_tt[4] = {1,3,4,6};
__constant__ int c_hh[4] = {4,12,19,27};

__device__ __forceinline__ int flat_idx(int n){
    int it = n >> 4, ih = (n >> 2) & 3, iw = n & 3;
    return (c_tt[it]*H_ + c_hh[ih])*W_ + c_hh[iw];
}
__device__ __forceinline__ float sigmoidf_(float x){ return 1.0f/(1.0f+expf(-x)); }
__device__ __forceinline__ float invsigf_(float x){
    return logf(fmaxf(x,1e-5f)/fmaxf(1.0f-x,1e-5f));
}
__device__ __forceinline__ void cp_async16(void* smem_dst, const void* gmem_src){
    unsigned s = (unsigned)__cvta_generic_to_shared(smem_dst);
    asm volatile("cp.async.cg.shared.global [%0], [%1], 16;\n" :: "r"(s), "l"(gmem_src));
}
__device__ __forceinline__ void cp_commit(){ asm volatile("cp.async.commit_group;\n"); }
__device__ __forceinline__ void cp_wait0(){ asm volatile("cp.async.wait_group 0;\n"); }
__device__ __forceinline__ void cp_wait1(){ asm volatile("cp.async.wait_group 1;\n"); }

typedef unsigned long long ull;
__device__ __forceinline__ ull fma2_(ull a, ull b, ull c){
    ull d; asm("fma.rn.f32x2 %0, %1, %2, %3;" : "=l"(d) : "l"(a), "l"(b), "l"(c)); return d;
}
__device__ __forceinline__ ull pack2_(float x, float y){
    ull r; asm("mov.b64 %0, {%1, %2};" : "=l"(r) : "f"(x), "f"(y)); return r;
}
__device__ __forceinline__ float2 unpack2_(ull v){
    float2 r; asm("mov.b64 {%0, %1}, %2;" : "=f"(r.x), "=f"(r.y) : "l"(v)); return r;
}

__device__ __forceinline__ void global_bar(){
    __syncthreads();
    if (threadIdx.x == 0){
        __threadfence();
        unsigned old  = atomicAdd(&g_barrier[0], 1u);
        unsigned goal = old - (old % (unsigned)NB) + (unsigned)NB;
        volatile unsigned* p = &g_barrier[0];
        while ((int)(*p - goal) < 0){}
        __threadfence();
    }
    __syncthreads();
}
__device__ __forceinline__ void group_bar(int id, int g){
    __syncthreads();
    if (threadIdx.x == 0){
        __threadfence();
        unsigned* cnt = &g_gbar[id][g*64];
        unsigned old  = atomicAdd(cnt, 1u);
        unsigned goal = old - (old % (unsigned)NBG) + (unsigned)NBG;
        volatile unsigned* p = cnt;
        while ((int)(*p - goal) < 0){}
        __threadfence();
    }
    __syncthreads();
}

// ============================================================
// GEMM phase (register-tiled, k-split): Out = relu(X @ W + bias [+ G])
// ============================================================
#define XD_ULL 2048
#define WF_F   4096

__device__ __forceinline__ void prime_W(const float* __restrict__ Wg, float* Wf,
                                        int c0, int t){
    #pragma unroll
    for (int u = 0; u < 2; u++){
        int idx4 = t + u*512;
        int wk = idx4 >> 3, ws = idx4 & 7;
        cp_async16(Wf + wk*32 + ws*4, Wg + (size_t)wk*256 + c0 + ws*4);
    }
    cp_commit();
}

template<int NCH, bool WRITE_T>
__device__ __forceinline__ void gemm_phase(
    const float* __restrict__ XT, const float* __restrict__ Wg,
    const float* __restrict__ bias, const float* Gadd,
    float* __restrict__ Out, ull* Xd, float* Wf)
{
    int t  = threadIdx.x;
    int c0 = (blockIdx.x & 7) * 32;
    int r0 = (blockIdx.x >> 3) * 16;
    int rp = t & 7, qc = (t >> 3) & 7, ks = t >> 6;
    int kk = t >> 2, seg = t & 3;

    {
        float4 xv = *(const float4*)(XT + (size_t)kk*256 + r0 + seg*4);
        ull* dst = Xd + kk*16 + seg*4;
        ulonglong2 d0, d1;
        d0.x = pack2_(xv.x, xv.x); d0.y = pack2_(xv.y, xv.y);
        d1.x = pack2_(xv.z, xv.z); d1.y = pack2_(xv.w, xv.w);
        *(ulonglong2*)dst = d0;
        *(ulonglong2*)(dst+2) = d1;
    }

    ull aA0=0ULL, aA1=0ULL, aB0=0ULL, aB1=0ULL;
    float4 xn;

    #pragma unroll 1
    for (int ch = 0; ch < NCH; ch++){
        ull*   Xc = Xd + (ch & 1)*XD_ULL;
        float* Wc = Wf + (ch & 1)*WF_F;
        if (ch + 1 < NCH){
            float* Wn2 = Wf + ((ch+1)&1)*WF_F;
            #pragma unroll
            for (int u = 0; u < 2; u++){
                int idx4 = t + u*512;
                int wk = idx4 >> 3, ws = idx4 & 7;
                cp_async16(Wn2 + wk*32 + ws*4,
                           Wg + (size_t)((ch+1)*128 + wk)*256 + c0 + ws*4);
            }
            cp_commit();
            xn = *(const float4*)(XT + (size_t)((ch+1)*128 + kk)*256 + r0 + seg*4);
            cp_wait1();
        } else {
            cp_wait0();
        }
        __syncthreads();

        const ull*   xb = Xc + (ks*16)*16 + 2*rp;
        const float* wb = Wc + (ks*16)*32 + qc*4;
        #pragma unroll 4
        for (int k2 = 0; k2 < 16; k2++){
            ulonglong2 xd = *(const ulonglong2*)(xb + k2*16);
            ulonglong2 wv = *(const ulonglong2*)(wb + k2*32);
            aA0 = fma2_(wv.x, xd.x, aA0);
            aA1 = fma2_(wv.y, xd.x, aA1);
            aB0 = fma2_(wv.x, xd.y, aB0);
            aB1 = fma2_(wv.y, xd.y, aB1);
        }
        __syncthreads();

        if (ch + 1 < NCH){
            ull* dst = Xd + ((ch+1)&1)*XD_ULL + kk*16 + seg*4;
            ulonglong2 d0, d1;
            d0.x = pack2_(xn.x, xn.x); d0.y = pack2_(xn.y, xn.y);
            d1.x = pack2_(xn.z, xn.z); d1.y = pack2_(xn.w, xn.w);
            *(ulonglong2*)dst = d0;
            *(ulonglong2*)(dst+2) = d1;
        }
    }

    ull* PART = Xd;
    {
        ull* dst = PART + (((ks<<6) + (t & 63))<<2);
        ulonglong2 p0, p1;
        p0.x = aA0; p0.y = aA1;
        p1.x = aB0; p1.y = aB1;
        *(ulonglong2*)dst = p0;
        *(ulonglong2*)(dst+2) = p1;
    }
    __syncthreads();

    if (t < 64){
        int pos = t, prp = pos & 7, pqc = pos >> 3;
        float2 e01 = make_float2(0.f,0.f), e23 = e01, o01 = e01, o23 = e01;
        #pragma unroll
        for (int s = 0; s < 8; s++){
            const ull* e = PART + (((s<<6) + pos)<<2);
            ulonglong2 u0 = *(const ulonglong2*)e;
            ulonglong2 u1 = *(const ulonglong2*)(e+2);
            float2 f;
            f = unpack2_(u0.x); e01.x += f.x; e01.y += f.y;
            f = unpack2_(u0.y); e23.x += f.x; e23.y += f.y;
            f = unpack2_(u1.x); o01.x += f.x; o01.y += f.y;
            f = unpack2_(u1.y); o23.x += f.x; o23.y += f.y;
        }
        float4 bb = *(const float4*)(bias + c0 + pqc*4);
        if (Gadd){
            bb.x += Gadd[pqc*4+0]; bb.y += Gadd[pqc*4+1];
            bb.z += Gadd[pqc*4+2]; bb.w += Gadd[pqc*4+3];
        }
        float ve0 = fmaxf(e01.x + bb.x, 0.f), ve1 = fmaxf(e01.y + bb.y, 0.f);
        float ve2 = fmaxf(e23.x + bb.z, 0.f), ve3 = fmaxf(e23.y + bb.w, 0.f);
        float vo0 = fmaxf(o01.x + bb.x, 0.f), vo1 = fmaxf(o01.y + bb.y, 0.f);
        float vo2 = fmaxf(o23.x + bb.z, 0.f), vo3 = fmaxf(o23.y + bb.w, 0.f);
        int re = r0 + 2*prp, cA = c0 + pqc*4;
        if (WRITE_T){
            *(float2*)(Out + (size_t)(cA+0)*256 + re) = make_float2(ve0, vo0);
            *(float2*)(Out + (size_t)(cA+1)*256 + re) = make_float2(ve1, vo1);
            *(float2*)(Out + (size_t)(cA+2)*256 + re) = make_float2(ve2, vo2);
            *(float2*)(Out + (size_t)(cA+3)*256 + re) = make_float2(ve3, vo3);
        } else {
            *(float4*)(Out + (size_t)re*256 + cA)     = make_float4(ve0, ve1, ve2, ve3);
            *(float4*)(Out + (size_t)(re+1)*256 + cA) = make_float4(vo0, vo1, vo2, vo3);
        }
    }
    __syncthreads();
}

// ============================================================
#define FUSED_SMEM_BYTES 65536

__global__ void __launch_bounds__(512, 1)
fused_kernel(const float* __restrict__ feats, const float* __restrict__ pos,
             const float* __restrict__ W1, const float* __restrict__ b1,
             const float* __restrict__ W2, const float* __restrict__ b2,
             const float* __restrict__ Wn, const float* __restrict__ bn,
             const float* __restrict__ Woff, const float* __restrict__ boff,
             const float* __restrict__ Ww, const float* __restrict__ bw,
             const float* __restrict__ gamma, const float* __restrict__ beta,
             float* __restrict__ out, int write_next)
{
    extern __shared__ ull smu[];
    ull*   Xd = smu;                        // 2 * 2048 ull
    float* Wf = (float*)(smu + 2*XD_ULL);   // 2 * 4096 floats

    __shared__ float  Hs2[2][256];
    __shared__ float  HWn[768], HWo[192], HWw[128];
    __shared__ float  HD2[2][28];
    __shared__ float  SPx[2][4], SPy[2][4], SPz[2][4], SPw[2][4];
    __shared__ int    cq2[2][40];
    __shared__ float  cw2[2][40];
    __shared__ int    nq2[2];
    __shared__ float2 sred2[2][8];
    __shared__ float  s_mu[2], s_rstd[2];
    __shared__ float  Gpart[256], Gs[32], glS[256];

    int t = threadIdx.x;
    int b = blockIdx.x;
    int g = b >> 3;
    int c0 = (b & 7) * 32;
    int l_blk = b >> 5;

    prime_W(W1, Wf, c0, t);     // W1 chunk 0: overlaps prep+fill+bar

    int half = t >> 8;
    int tt   = t & 255;
    int cch  = 2*b + half;      // this thread's scan channel

    // ---- phase A1: small XT gathers (feat|pos, k<512)
    {
        int l = tt >> 6;
        int p = flat_idx(tt & 63);
        float fv = feats[((size_t)cch*THW_ + p)*L_ + l];
        float pv = pos  [((size_t)cch*THW_ + p)*L_ + l];
        g_XT[(size_t)cch*256 + tt]       = fv;
        g_XT[(size_t)(256+cch)*256 + tt] = pv;
    }

    // ---- phase A2: channel-mean scan, 4 independent float4 chains
    {
        const float4* f4 = reinterpret_cast<const float4*>(feats + (size_t)cch*(THW_*L_));
        float4 a0 = make_float4(0,0,0,0), a1 = a0, a2 = a0, a3 = a0;
        #pragma unroll
        for (int j = 0; j < 8; j++){
            float4 v0 = f4[tt + (4*j+0)*256];
            float4 v1 = f4[tt + (4*j+1)*256];
            float4 v2 = f4[tt + (4*j+2)*256];
            float4 v3 = f4[tt + (4*j+3)*256];
            a0.x+=v0.x; a0.y+=v0.y; a0.z+=v0.z; a0.w+=v0.w;
            a1.x+=v1.x; a1.y+=v1.y; a1.z+=v1.z; a1.w+=v1.w;
            a2.x+=v2.x; a2.y+=v2.y; a2.z+=v2.z; a2.w+=v2.w;
            a3.x+=v3.x; a3.y+=v3.y; a3.z+=v3.z; a3.w+=v3.w;
        }
        float4 a = make_float4(a0.x+a1.x+a2.x+a3.x, a0.y+a1.y+a2.y+a3.y,
                               a0.z+a1.z+a2.z+a3.z, a0.w+a1.w+a2.w+a3.w);
        const unsigned full = 0xffffffffu;
        #pragma unroll
        for (int o = 16; o > 0; o >>= 1){
            a.x += __shfl_xor_sync(full, a.x, o);
            a.y += __shfl_xor_sync(full, a.y, o);
            a.z += __shfl_xor_sync(full, a.z, o);
            a.w += __shfl_xor_sync(full, a.w, o);
        }
        float4* sm4 = (float4*)smu;      // overlays Xd (free until GEMM1)
        int wid = t >> 5, lane = t & 31;
        if (lane == 0) sm4[wid] = a;
        __syncthreads();
        if (t < 2){
            float4 s = make_float4(0,0,0,0);
            #pragma unroll
            for (int w2 = 0; w2 < 8; w2++){
                float4 v = sm4[t*8 + w2];
                s.x+=v.x; s.y+=v.y; s.z+=v.z; s.w+=v.w;
            }
            const float inv = 1.0f/8192.0f;
            int c = 2*b + t;
            g_glob[0*256+c] = s.x*inv;
            g_glob[1*256+c] = s.y*inv;
            g_glob[2*256+c] = s.z*inv;
            g_glob[3*256+c] = s.w*inv;
        }
    }

    // ---- phase B: beta fill (skips sampled positions) — overlaps bar skew
    {
        float4* out4 = (float4*)out;
        const unsigned tm = 0x5Au;
        const unsigned hm = (1u<<4)|(1u<<12)|(1u<<19)|(1u<<27);
        #pragma unroll
        for (int u = 0; u < 8; u++){
            int f = b*4096 + u*512 + t;
            int c = f >> 13;
            int p = f & 8191;
            int t3 = p >> 10, h3 = (p >> 5) & 31, w3 = p & 31;
            bool samp = ((tm >> t3) & 1u) && ((hm >> h3) & 1u) && ((hm >> w3) & 1u);
            if (!samp){
                float bb = __ldg(&beta[c]);
                out4[f] = make_float4(bb, bb, bb, bb);
            }
        }
    }

    global_bar();                       // XT + g_glob complete chip-wide

    // ---- phase C0: G[j] = sum_c glob[l_blk][c] * W1[512+c][c0+j]
    if (t < 256) glS[t] = g_glob[l_blk*256 + t];
    __syncthreads();
    if (t < 256){
        int j = t & 31, cs = t >> 5;
        const float* wp = W1 + (size_t)(512 + cs*32)*256 + c0 + j;
        float s0 = 0.f, s1 = 0.f;
        #pragma unroll
        for (int ci = 0; ci < 32; ci += 2){
            s0 = fmaf(glS[cs*32+ci],   wp[(size_t)ci*256],     s0);
            s1 = fmaf(glS[cs*32+ci+1], wp[(size_t)(ci+1)*256], s1);
        }
        Gpart[cs*32 + j] = s0 + s1;
    }
    __syncthreads();
    if (t < 32){
        float s = 0.f;
        #pragma unroll
        for (int cs = 0; cs < 8; cs++) s += Gpart[cs*32 + t];
        Gs[t] = s;
    }
    __syncthreads();

    // ---- phase C: GEMM1 (K=512) -> g_H1T  (+G bias fold)
    gemm_phase<4, true>(g_XT, W1, b1, Gs, g_H1T, Xd, Wf);

    prime_W(W2, Wf, c0, t);
    group_bar(0, g);

    // ---- phase D: GEMM2 (K=256) -> g_H2
    gemm_phase<2, false>(g_H1T, W2, b2, nullptr, g_H2, Xd, Wf);
    group_bar(1, g);

    // ---- phase E: heads + dedup, rows 2b / 2b+1
    int row = t >> 8;
    int u   = t & 255;
    int rr  = b*2 + row;
    int p   = flat_idx(rr & 63);

    Hs2[row][u] = g_H2[(size_t)rr*256 + u];
    for (int k = t; k < 768; k += 512) HWn[k] = Wn[k];
    if (t < 192) HWo[t] = Woff[t];
    if (t >= 256 && t < 384) HWw[t-256] = Ww[t-256];
    __syncthreads();

    if (u < 3){
        float s = bn[u];
        #pragma unroll 8
        for (int k = 0; k < 256; k++) s = fmaf(Hs2[row][k], HWn[k*3 + u], s);
        HD2[row][u] = s;
    } else if (u >= 8 && u < 20){
        int v = u - 8;
        int no = v / 3, jo = v - no*3;
        float s = boff[jo];
        #pragma unroll 8
        for (int dd = 0; dd < 64; dd++) s = fmaf(Hs2[row][no*64+dd], HWo[dd*3 + jo], s);
        HD2[row][8+v] = s;
    } else if (u >= 20 && u < 28){
        int v = u - 20;
        int no = v >> 1, comp = v & 1;
        float s = bw[comp];
        #pragma unroll 8
        for (int dd = 0; dd < 64; dd++) s = fmaf(Hs2[row][no*64+dd], HWw[dd*2 + comp], s);
        HD2[row][20+v] = s;
    }
    __syncthreads();

    if (u == 0){
        int tq = p >> 10, hq = (p >> 5) & 31, wq = p & 31;
        float tn = (float)tq * (1.0f/7.0f);
        float hn = (float)hq * (1.0f/31.0f);
        float wn = (float)wq * (1.0f/31.0f);
        float ivt = invsigf_(tn), ivh = invsigf_(hn), ivw = invsigf_(wn);

        #pragma unroll
        for (int no = 0; no < 4; no++){
            float o0 = HD2[row][8+no*3+0], o1 = HD2[row][8+no*3+1], o2 = HD2[row][8+no*3+2];
            float st = sigmoidf_(ivt + o0)*2.0f - 1.0f;
            float sh = sigmoidf_(ivh + o1)*2.0f - 1.0f;
            float sw = sigmoidf_(ivw + o2)*2.0f - 1.0f;
            SPx[row][no] = ((st + 1.0f)*32.0f - 1.0f)*0.5f;
            SPy[row][no] = ((sh + 1.0f)*32.0f - 1.0f)*0.5f;
            SPz[row][no] = ((sw + 1.0f)*8.0f  - 1.0f)*0.5f;
            float za = HD2[row][20+no*2], zb = HD2[row][21+no*2];
            SPw[row][no] = 1.0f/(1.0f + expf(za - zb));
        }

        if (write_next){
            float d0 = sigmoidf_(ivt + HD2[row][0]) * 7.0f;
            float d1 = sigmoidf_(ivh + HD2[row][1]) * 31.0f;
            float d2 = sigmoidf_(ivw + HD2[row][2]) * 31.0f;
            int ni = 1024*(int)rintf(d0) + 32*(int)rintf(d1) + (int)rintf(d2);
            out[FEAT_OUT_ELEMS + rr] = (float)ni;
        }
    }
    __syncthreads();

    if (u < 32){
        const unsigned full = 0xffffffffu;
        int lane = t & 31;
        int no = lane >> 3, jj = lane & 7;
        float ix = SPx[row][no], iy = SPy[row][no], iz = SPz[row][no];
        float wo = SPw[row][no];
        float x0f = floorf(ix), y0f = floorf(iy), z0f = floorf(iz);
        int dx = jj & 1, dy = (jj >> 1) & 1, dz = jj >> 2;
        int xi = (int)x0f + dx, yi = (int)y0f + dy, zi = (int)z0f + dz;
        float fx = ix - x0f, fy = iy - y0f, fz = iz - z0f;
        float w = (dx ? fx : 1.0f-fx) * (dy ? fy : 1.0f-fy) * (dz ? fz : 1.0f-fz) * wo;
        bool valid = (xi >= 0) & (xi < W_) & (yi >= 0) & (yi < H_) & (zi >= 0) & (zi < T_);
        if (!valid) w = 0.0f;
        int q = (min(max(zi,0),T_-1)*H_ + min(max(yi,0),H_-1))*W_ + min(max(xi,0),W_-1);

        unsigned mask = __match_any_sync(full, q);
        float wsum = 0.0f;
        #pragma unroll
        for (int s2 = 0; s2 < 32; s2++){
            float wv = __shfl_sync(full, w, s2);
            int   qv = __shfl_sync(full, q, s2);
            if (qv == q) wsum += wv;
        }
        int leader = __ffs(mask) - 1;
        bool is_leader = (lane == leader);
        unsigned bal = __ballot_sync(full, is_leader);
        int pos = __popc(bal & ((1u << lane) - 1u));
        if (is_leader){ cq2[row][pos] = q; cw2[row][pos] = wsum; }
        __syncwarp();
        if (lane == 0){
            int nq = __popc(bal);
            bool found = false;
            for (int j2 = 0; j2 < nq; j2++){
                if (cq2[row][j2] == p){ cw2[row][j2] += 1.0f; found = true; break; }
            }
            if (!found){ cq2[row][nq] = p; cw2[row][nq] = 1.0f; nq++; }
            nq2[row] = nq;
        }
    }
    __syncthreads();

    // ---- phase F: sample + LN
    {
        int l  = rr >> 6;
        int c  = u;
        int nq = nq2[row];
        const float* fb = feats + (size_t)c*(THW_*L_) + l;
        float acc = 0.0f;
        #pragma unroll 4
        for (int j2 = 0; j2 < nq; j2++)
            acc = fmaf(cw2[row][j2], __ldg(fb + (size_t)cq2[row][j2]*L_), acc);
        float v = acc;

        const unsigned full = 0xffffffffu;
        float sx = v, sy = v*v;
        #pragma unroll
        for (int o = 16; o > 0; o >>= 1){
            sx += __shfl_xor_sync(full, sx, o);
            sy += __shfl_xor_sync(full, sy, o);
        }
        int lane = t & 31;
        int wrp  = (t >> 5) & 7;
        if (lane == 0) sred2[row][wrp] = make_float2(sx, sy);
        __syncthreads();
        if (u == 0){
            float mx = 0.f, my = 0.f;
            #pragma unroll
            for (int k = 0; k < 8; k++){ mx += sred2[row][k].x; my += sred2[row][k].y; }
            float mu  = mx * (1.0f/256.0f);
            float var = my * (1.0f/256.0f) - mu*mu;
            s_mu[row] = mu;
            s_rstd[row] = rsqrtf(var + 1e-5f);
        }
        __syncthreads();

        float o = (v - s_mu[row]) * s_rstd[row] * __ldg(&gamma[c]) + __ldg(&beta[c]);
        out[((size_t)c*THW_ + p)*L_ + l] = o;
    }
}

// ============================================================
extern "C" void kernel_launch(void* const* d_in, const int* in_sizes, int n_in,
                              void* d_out, int out_size)
{
    const float* feats = (const float*)d_in[0];
    const float* pos   = (const float*)d_in[1];
    const float* W1    = (const float*)d_in[2];
    const float* b1    = (const float*)d_in[3];
    const float* W2    = (const float*)d_in[4];
    const float* b2    = (const float*)d_in[5];
    const float* Wn    = (const float*)d_in[6];
    const float* bn    = (const float*)d_in[7];
    // d_in[8]=Wl, d_in[9]=bl dead (softmax row-sum == 1; LN scale-invariant)
    const float* Woff  = (const float*)d_in[10];
    const float* boff  = (const float*)d_in[11];
    const float* Ww    = (const float*)d_in[12];
    const float* bw    = (const float*)d_in[13];
    const float* gamma = (const float*)d_in[14];
    const float* beta  = (const float*)d_in[15];
    float* out = (float*)d_out;

    int write_next = (out_size >= FEAT_OUT_ELEMS + NROWS) ? 1 : 0;

    static int smem_set = 0;
    if (!smem_set){
        cudaFuncSetAttribute(fused_kernel, cudaFuncAttributeMaxDynamicSharedMemorySize,
                             FUSED_SMEM_BYTES);
        smem_set = 1;
    }

    fused_kernel<<<NB, 512, FUSED_SMEM_BYTES>>>(feats, pos, W1, b1, W2, b2, Wn, bn,
                                                Woff, boff, Ww, bw, gamma, beta,
                                                out, write_next);
}

// round 13
// speedup vs baseline: 1.6166x; 1.0777x over previous
#include <cuda_runtime.h>
#include <math.h>

#define C_    256
#define T_    8
#define H_    32
#define W_    32
#define L_    4
#define THW_  8192
#define NROWS 256
#define FEAT_OUT_ELEMS (C_*THW_*L_)   // 2097152
#define NB 256                        // 256 blocks x 256 threads, 2/SM co-resident
#define NBG 8

// ---- scratch (device globals; no allocation) ----
__device__ float    g_XT [512*256];    // X transposed (feat|pos): [k][row]
__device__ float    g_H1T[256*256];    // H1 transposed: [k][row]
__device__ float    g_H2 [256*256];    // H2 row-major
__device__ float    g_glob[4*256];
__device__ unsigned g_barrier[1];
__device__ unsigned g_gbar[2][32*64];

__constant__ int c_tt[4] = {1,3,4,6};
__constant__ int c_hh[4] = {4,12,19,27};

__device__ __forceinline__ int flat_idx(int n){
    int it = n >> 4, ih = (n >> 2) & 3, iw = n & 3;
    return (c_tt[it]*H_ + c_hh[ih])*W_ + c_hh[iw];
}
__device__ __forceinline__ float sigmoidf_(float x){ return 1.0f/(1.0f+expf(-x)); }
__device__ __forceinline__ float invsigf_(float x){
    return logf(fmaxf(x,1e-5f)/fmaxf(1.0f-x,1e-5f));
}
__device__ __forceinline__ void cp_async16(void* smem_dst, const void* gmem_src){
    unsigned s = (unsigned)__cvta_generic_to_shared(smem_dst);
    asm volatile("cp.async.cg.shared.global [%0], [%1], 16;\n" :: "r"(s), "l"(gmem_src));
}
__device__ __forceinline__ void cp_commit(){ asm volatile("cp.async.commit_group;\n"); }
__device__ __forceinline__ void cp_wait0(){ asm volatile("cp.async.wait_group 0;\n"); }
__device__ __forceinline__ void cp_wait1(){ asm volatile("cp.async.wait_group 1;\n"); }

typedef unsigned long long ull;
__device__ __forceinline__ ull fma2_(ull a, ull b, ull c){
    ull d; asm("fma.rn.f32x2 %0, %1, %2, %3;" : "=l"(d) : "l"(a), "l"(b), "l"(c)); return d;
}
__device__ __forceinline__ ull pack2_(float x, float y){
    ull r; asm("mov.b64 %0, {%1, %2};" : "=l"(r) : "f"(x), "f"(y)); return r;
}
__device__ __forceinline__ float2 unpack2_(ull v){
    float2 r; asm("mov.b64 {%0, %1}, %2;" : "=f"(r.x), "=f"(r.y) : "l"(v)); return r;
}

__device__ __forceinline__ void global_bar(){
    __syncthreads();
    if (threadIdx.x == 0){
        __threadfence();
        unsigned old  = atomicAdd(&g_barrier[0], 1u);
        unsigned goal = old - (old % (unsigned)NB) + (unsigned)NB;
        volatile unsigned* p = &g_barrier[0];
        while ((int)(*p - goal) < 0){}
        __threadfence();
    }
    __syncthreads();
}
__device__ __forceinline__ void group_bar(int id, int g){
    __syncthreads();
    if (threadIdx.x == 0){
        __threadfence();
        unsigned* cnt = &g_gbar[id][g*64];
        unsigned old  = atomicAdd(cnt, 1u);
        unsigned goal = old - (old % (unsigned)NBG) + (unsigned)NBG;
        volatile unsigned* p = cnt;
        while ((int)(*p - goal) < 0){}
        __threadfence();
    }
    __syncthreads();
}

// ============================================================
// GEMM phase: Out = relu(X[256,K] @ W[K,256] + bias [+G])
// X k-major. 256 blocks x 256 threads; tile 8 rows x 32 cols.
// thread = (rp=t&3 rowpair, qc=(t>>2)&7 colquad, ks=t>>5 ksplit/8).
// smem: Xd 2x1024 ull (x pre-dup), Wf 2x4096 floats. PART aliases Xd buf0.
// ============================================================
#define XD_ULL 1024
#define WF_F   4096

__device__ __forceinline__ void prime_W(const float* __restrict__ Wg, float* Wf,
                                        int c0, int t){
    #pragma unroll
    for (int u = 0; u < 4; u++){
        int idx4 = t + u*256;
        int wk = idx4 >> 3, ws = idx4 & 7;
        cp_async16(Wf + wk*32 + ws*4, Wg + (size_t)wk*256 + c0 + ws*4);
    }
    cp_commit();
}

template<int NCH, bool WRITE_T>
__device__ __forceinline__ void gemm_phase(
    const float* __restrict__ XT, const float* __restrict__ Wg,
    const float* __restrict__ bias, const float* Gadd,
    float* __restrict__ Out, ull* Xd, float* Wf)
{
    int t  = threadIdx.x;
    int c0 = ((int)blockIdx.x & 7) * 32;
    int r0 = ((int)blockIdx.x >> 3) * 8;
    int rp = t & 3, qc = (t >> 2) & 7, ks = t >> 5;
    int kk = t >> 1, seg = t & 1;

    // X prime chunk 0 (W chunk 0 primed by caller)
    {
        float4 xv = *(const float4*)(XT + (size_t)kk*256 + r0 + seg*4);
        ull* dst = Xd + kk*8 + seg*4;
        ulonglong2 d0, d1;
        d0.x = pack2_(xv.x, xv.x); d0.y = pack2_(xv.y, xv.y);
        d1.x = pack2_(xv.z, xv.z); d1.y = pack2_(xv.w, xv.w);
        *(ulonglong2*)dst = d0;
        *(ulonglong2*)(dst+2) = d1;
    }

    ull aA0=0ULL, aA1=0ULL, aB0=0ULL, aB1=0ULL;
    float4 xn;

    #pragma unroll 1
    for (int ch = 0; ch < NCH; ch++){
        ull*   Xc = Xd + (ch & 1)*XD_ULL;
        float* Wc = Wf + (ch & 1)*WF_F;
        if (ch + 1 < NCH){
            float* Wn2 = Wf + ((ch+1)&1)*WF_F;
            #pragma unroll
            for (int u = 0; u < 4; u++){
                int idx4 = t + u*256;
                int wk = idx4 >> 3, ws = idx4 & 7;
                cp_async16(Wn2 + wk*32 + ws*4,
                           Wg + (size_t)((ch+1)*128 + wk)*256 + c0 + ws*4);
            }
            cp_commit();
            xn = *(const float4*)(XT + (size_t)((ch+1)*128 + kk)*256 + r0 + seg*4);
            cp_wait1();
        } else {
            cp_wait0();
        }
        __syncthreads();

        const ull*   xb = Xc + (ks*16)*8 + 2*rp;
        const float* wb = Wc + (ks*16)*32 + qc*4;
        #pragma unroll 4
        for (int k2 = 0; k2 < 16; k2++){
            ulonglong2 xd = *(const ulonglong2*)(xb + k2*8);
            ulonglong2 wv = *(const ulonglong2*)(wb + k2*32);
            aA0 = fma2_(wv.x, xd.x, aA0);
            aA1 = fma2_(wv.y, xd.x, aA1);
            aB0 = fma2_(wv.x, xd.y, aB0);
            aB1 = fma2_(wv.y, xd.y, aB1);
        }
        __syncthreads();

        if (ch + 1 < NCH){
            ull* dst = Xd + ((ch+1)&1)*XD_ULL + kk*8 + seg*4;
            ulonglong2 d0, d1;
            d0.x = pack2_(xn.x, xn.x); d0.y = pack2_(xn.y, xn.y);
            d1.x = pack2_(xn.z, xn.z); d1.y = pack2_(xn.w, xn.w);
            *(ulonglong2*)dst = d0;
            *(ulonglong2*)(dst+2) = d1;
        }
    }

    // k-split reduction (PART = Xd buffer 0; last chunk computed from buf 1)
    ull* PART = Xd;
    {
        ull* dst = PART + (size_t)t*4;
        ulonglong2 p0, p1;
        p0.x = aA0; p0.y = aA1;
        p1.x = aB0; p1.y = aB1;
        *(ulonglong2*)dst = p0;
        *(ulonglong2*)(dst+2) = p1;
    }
    __syncthreads();

    if (t < 32){
        int prp = t & 3, pqc = (t >> 2) & 7;
        float2 e01 = make_float2(0.f,0.f), e23 = e01, o01 = e01, o23 = e01;
        #pragma unroll
        for (int s = 0; s < 8; s++){
            const ull* e = PART + (size_t)(s*32 + t)*4;
            ulonglong2 u0 = *(const ulonglong2*)e;
            ulonglong2 u1 = *(const ulonglong2*)(e+2);
            float2 f;
            f = unpack2_(u0.x); e01.x += f.x; e01.y += f.y;
            f = unpack2_(u0.y); e23.x += f.x; e23.y += f.y;
            f = unpack2_(u1.x); o01.x += f.x; o01.y += f.y;
            f = unpack2_(u1.y); o23.x += f.x; o23.y += f.y;
        }
        float4 bb = *(const float4*)(bias + c0 + pqc*4);
        if (Gadd){
            bb.x += Gadd[pqc*4+0]; bb.y += Gadd[pqc*4+1];
            bb.z += Gadd[pqc*4+2]; bb.w += Gadd[pqc*4+3];
        }
        float ve0 = fmaxf(e01.x + bb.x, 0.f), ve1 = fmaxf(e01.y + bb.y, 0.f);
        float ve2 = fmaxf(e23.x + bb.z, 0.f), ve3 = fmaxf(e23.y + bb.w, 0.f);
        float vo0 = fmaxf(o01.x + bb.x, 0.f), vo1 = fmaxf(o01.y + bb.y, 0.f);
        float vo2 = fmaxf(o23.x + bb.z, 0.f), vo3 = fmaxf(o23.y + bb.w, 0.f);
        int re = r0 + 2*prp, cA = c0 + pqc*4;
        if (WRITE_T){
            *(float2*)(Out + (size_t)(cA+0)*256 + re) = make_float2(ve0, vo0);
            *(float2*)(Out + (size_t)(cA+1)*256 + re) = make_float2(ve1, vo1);
            *(float2*)(Out + (size_t)(cA+2)*256 + re) = make_float2(ve2, vo2);
            *(float2*)(Out + (size_t)(cA+3)*256 + re) = make_float2(ve3, vo3);
        } else {
            *(float4*)(Out + (size_t)re*256 + cA)     = make_float4(ve0, ve1, ve2, ve3);
            *(float4*)(Out + (size_t)(re+1)*256 + cA) = make_float4(vo0, vo1, vo2, vo3);
        }
    }
    __syncthreads();
}

// ============================================================
#define FUSED_SMEM_BYTES 49152   // Xd 2x1024 ull + Wf 2x4096 f = 48KB

__global__ void __launch_bounds__(256, 2)
fused_kernel(const float* __restrict__ feats, const float* __restrict__ pos,
             const float* __restrict__ W1, const float* __restrict__ b1,
             const float* __restrict__ W2, const float* __restrict__ b2,
             const float* __restrict__ Wn, const float* __restrict__ bn,
             const float* __restrict__ Woff, const float* __restrict__ boff,
             const float* __restrict__ Ww, const float* __restrict__ bw,
             const float* __restrict__ gamma, const float* __restrict__ beta,
             float* __restrict__ out, int write_next)
{
    extern __shared__ ull smu[];
    ull*   Xd = smu;                        // 2 * 1024 ull
    float* Wf = (float*)(smu + 2*XD_ULL);   // 2 * 4096 floats

    __shared__ float  Hs[256];
    __shared__ float  HWn[768], HWo[192], HWw[128];
    __shared__ float  HD[28];
    __shared__ float  SPx[4], SPy[4], SPz[4], SPw[4];
    __shared__ int    cq[40];
    __shared__ float  cw[40];
    __shared__ int    s_nq;
    __shared__ float2 sred[8];
    __shared__ float  s_mu, s_rstd;
    __shared__ float  Gpart[256], Gs[32], glS[256];

    int t = threadIdx.x;
    int b = blockIdx.x;
    int g = b >> 3;
    int c0 = (b & 7) * 32;
    int l_blk = b >> 6;

    prime_W(W1, Wf, c0, t);         // W1 chunk 0 overlaps prep+fill+bar

    // ---- phase A1: XT gathers for channel b (feat | pos)
    {
        int l = t >> 6;
        int p = flat_idx(t & 63);
        g_XT[(size_t)b*256 + t]       = feats[((size_t)b*THW_ + p)*L_ + l];
        g_XT[(size_t)(256+b)*256 + t] = pos  [((size_t)b*THW_ + p)*L_ + l];
    }

    // ---- phase A2: channel-b mean scan, 4 independent float4 chains
    {
        const float4* f4 = reinterpret_cast<const float4*>(feats + (size_t)b*(THW_*L_));
        float4 a0 = make_float4(0,0,0,0), a1 = a0, a2 = a0, a3 = a0;
        #pragma unroll
        for (int j = 0; j < 8; j++){
            float4 v0 = f4[t + (4*j+0)*256];
            float4 v1 = f4[t + (4*j+1)*256];
            float4 v2 = f4[t + (4*j+2)*256];
            float4 v3 = f4[t + (4*j+3)*256];
            a0.x+=v0.x; a0.y+=v0.y; a0.z+=v0.z; a0.w+=v0.w;
            a1.x+=v1.x; a1.y+=v1.y; a1.z+=v1.z; a1.w+=v1.w;
            a2.x+=v2.x; a2.y+=v2.y; a2.z+=v2.z; a2.w+=v2.w;
            a3.x+=v3.x; a3.y+=v3.y; a3.z+=v3.z; a3.w+=v3.w;
        }
        float4 a = make_float4(a0.x+a1.x+a2.x+a3.x, a0.y+a1.y+a2.y+a3.y,
                               a0.z+a1.z+a2.z+a3.z, a0.w+a1.w+a2.w+a3.w);
        const unsigned full = 0xffffffffu;
        #pragma unroll
        for (int o = 16; o > 0; o >>= 1){
            a.x += __shfl_xor_sync(full, a.x, o);
            a.y += __shfl_xor_sync(full, a.y, o);
            a.z += __shfl_xor_sync(full, a.z, o);
            a.w += __shfl_xor_sync(full, a.w, o);
        }
        float4* sm4 = (float4*)smu;       // overlays Xd (free until GEMM1)
        int wid = t >> 5, lane = t & 31;
        if (lane == 0) sm4[wid] = a;
        __syncthreads();
        if (t == 0){
            float4 s = make_float4(0,0,0,0);
            #pragma unroll
            for (int w2 = 0; w2 < 8; w2++){
                float4 v = sm4[w2];
                s.x+=v.x; s.y+=v.y; s.z+=v.z; s.w+=v.w;
            }
            const float inv = 1.0f/8192.0f;
            g_glob[0*256+b] = s.x*inv;
            g_glob[1*256+b] = s.y*inv;
            g_glob[2*256+b] = s.z*inv;
            g_glob[3*256+b] = s.w*inv;
        }
    }

    // ---- phase B: beta fill (skips sampled positions)
    {
        float4* out4 = (float4*)out;
        const unsigned tm = 0x5Au;
        const unsigned hm = (1u<<4)|(1u<<12)|(1u<<19)|(1u<<27);
        #pragma unroll
        for (int u = 0; u < 8; u++){
            int f = b*2048 + u*256 + t;
            int c = f >> 13;
            int p = f & 8191;
            int t3 = p >> 10, h3 = (p >> 5) & 31, w3 = p & 31;
            bool samp = ((tm >> t3) & 1u) && ((hm >> h3) & 1u) && ((hm >> w3) & 1u);
            if (!samp){
                float bb = __ldg(&beta[c]);
                out4[f] = make_float4(bb, bb, bb, bb);
            }
        }
    }

    global_bar();                       // XT + g_glob complete chip-wide

    // ---- phase C0: G[j] = sum_c glob[l_blk][c] * W1[512+c][c0+j]
    glS[t] = g_glob[l_blk*256 + t];
    __syncthreads();
    {
        int j = t & 31, cs = t >> 5;
        const float* wp = W1 + (size_t)(512 + cs*32)*256 + c0 + j;
        float s0 = 0.f, s1 = 0.f;
        #pragma unroll
        for (int ci = 0; ci < 32; ci += 2){
            s0 = fmaf(glS[cs*32+ci],   wp[(size_t)ci*256],     s0);
            s1 = fmaf(glS[cs*32+ci+1], wp[(size_t)(ci+1)*256], s1);
        }
        Gpart[cs*32 + j] = s0 + s1;
    }
    __syncthreads();
    if (t < 32){
        float s = 0.f;
        #pragma unroll
        for (int cs = 0; cs < 8; cs++) s += Gpart[cs*32 + t];
        Gs[t] = s;
    }
    __syncthreads();

    // ---- phase C: GEMM1 (K=512) -> g_H1T  (+G bias fold)
    gemm_phase<4, true>(g_XT, W1, b1, Gs, g_H1T, Xd, Wf);

    prime_W(W2, Wf, c0, t);
    group_bar(0, g);

    // ---- phase D: GEMM2 (K=256) -> g_H2
    gemm_phase<2, false>(g_H1T, W2, b2, nullptr, g_H2, Xd, Wf);
    group_bar(1, g);

    // ---- phase E: heads (28 parallel 8-lane dots) + dedup, row rr = b
    int rr = b;
    int p  = flat_idx(rr & 63);

    Hs[t] = g_H2[(size_t)rr*256 + t];
    for (int k = t; k < 768; k += 256) HWn[k] = Wn[k];
    if (t < 192) HWo[t] = Woff[t];
    if (t < 128) HWw[t] = Ww[t];
    __syncthreads();

    {
        int oid = t >> 3, sl = t & 7;
        float s = 0.f;
        if (oid < 3){                         // nxt: 256-dot
            #pragma unroll 8
            for (int i = 0; i < 32; i++){
                int k = sl + 8*i;
                s = fmaf(Hs[k], HWn[k*3 + oid], s);
            }
        } else if (oid >= 8 && oid < 20){     // offsets: 64-dot
            int v = oid - 8;
            int no = v / 3, jo = v - no*3;
            #pragma unroll
            for (int i = 0; i < 8; i++){
                int dd = sl + 8*i;
                s = fmaf(Hs[no*64+dd], HWo[dd*3 + jo], s);
            }
        } else if (oid >= 20 && oid < 28){    // w_o: 64-dot
            int v = oid - 20;
            int no = v >> 1, comp = v & 1;
            #pragma unroll
            for (int i = 0; i < 8; i++){
                int dd = sl + 8*i;
                s = fmaf(Hs[no*64+dd], HWw[dd*2 + comp], s);
            }
        }
        const unsigned full = 0xffffffffu;
        s += __shfl_xor_sync(full, s, 4);
        s += __shfl_xor_sync(full, s, 2);
        s += __shfl_xor_sync(full, s, 1);
        if (sl == 0 && oid < 28) HD[oid] = s;
    }
    __syncthreads();

    if (t == 0){
        int tq = p >> 10, hq = (p >> 5) & 31, wq = p & 31;
        float tn = (float)tq * (1.0f/7.0f);
        float hn = (float)hq * (1.0f/31.0f);
        float wn = (float)wq * (1.0f/31.0f);
        float ivt = invsigf_(tn), ivh = invsigf_(hn), ivw = invsigf_(wn);
        float bo0 = boff[0], bo1 = boff[1], bo2 = boff[2];
        float bw0 = bw[0],  bw1 = bw[1];

        #pragma unroll
        for (int no = 0; no < 4; no++){
            float o0 = HD[8+no*3+0] + bo0;
            float o1 = HD[8+no*3+1] + bo1;
            float o2 = HD[8+no*3+2] + bo2;
            float st = sigmoidf_(ivt + o0)*2.0f - 1.0f;
            float sh = sigmoidf_(ivh + o1)*2.0f - 1.0f;
            float sw = sigmoidf_(ivw + o2)*2.0f - 1.0f;
            SPx[no] = ((st + 1.0f)*32.0f - 1.0f)*0.5f;
            SPy[no] = ((sh + 1.0f)*32.0f - 1.0f)*0.5f;
            SPz[no] = ((sw + 1.0f)*8.0f  - 1.0f)*0.5f;
            float za = HD[20+no*2] + bw0, zb = HD[21+no*2] + bw1;
            SPw[no] = 1.0f/(1.0f + expf(za - zb));
        }

        if (write_next){
            float d0 = sigmoidf_(ivt + HD[0] + bn[0]) * 7.0f;
            float d1 = sigmoidf_(ivh + HD[1] + bn[1]) * 31.0f;
            float d2 = sigmoidf_(ivw + HD[2] + bn[2]) * 31.0f;
            int ni = 1024*(int)rintf(d0) + 32*(int)rintf(d1) + (int)rintf(d2);
            out[FEAT_OUT_ELEMS + rr] = (float)ni;
        }
    }
    __syncthreads();

    if (t < 32){
        const unsigned full = 0xffffffffu;
        int lane = t;
        int no = lane >> 3, jj = lane & 7;
        float ix = SPx[no], iy = SPy[no], iz = SPz[no];
        float wo = SPw[no];
        float x0f = floorf(ix), y0f = floorf(iy), z0f = floorf(iz);
        int dx = jj & 1, dy = (jj >> 1) & 1, dz = jj >> 2;
        int xi = (int)x0f + dx, yi = (int)y0f + dy, zi = (int)z0f + dz;
        float fx = ix - x0f, fy = iy - y0f, fz = iz - z0f;
        float w = (dx ? fx : 1.0f-fx) * (dy ? fy : 1.0f-fy) * (dz ? fz : 1.0f-fz) * wo;
        bool valid = (xi >= 0) & (xi < W_) & (yi >= 0) & (yi < H_) & (zi >= 0) & (zi < T_);
        if (!valid) w = 0.0f;
        int q = (min(max(zi,0),T_-1)*H_ + min(max(yi,0),H_-1))*W_ + min(max(xi,0),W_-1);

        unsigned mask = __match_any_sync(full, q);
        float wsum = 0.0f;
        #pragma unroll
        for (int s2 = 0; s2 < 32; s2++){
            float wv = __shfl_sync(full, w, s2);
            int   qv = __shfl_sync(full, q, s2);
            if (qv == q) wsum += wv;
        }
        int leader = __ffs(mask) - 1;
        bool is_leader = (lane == leader);
        unsigned bal = __ballot_sync(full, is_leader);
        int pos = __popc(bal & ((1u << lane) - 1u));
        if (is_leader){ cq[pos] = q; cw[pos] = wsum; }
        __syncwarp();
        if (lane == 0){
            int nq = __popc(bal);
            bool found = false;
            for (int j2 = 0; j2 < nq; j2++){
                if (cq[j2] == p){ cw[j2] += 1.0f; found = true; break; }
            }
            if (!found){ cq[nq] = p; cw[nq] = 1.0f; nq++; }
            s_nq = nq;
        }
    }
    __syncthreads();

    // ---- phase F: sample + LN, row rr
    {
        int l  = rr >> 6;
        int c  = t;
        int nq = s_nq;
        const float* fb = feats + (size_t)c*(THW_*L_) + l;
        float acc = 0.0f;
        #pragma unroll 4
        for (int j2 = 0; j2 < nq; j2++)
            acc = fmaf(cw[j2], __ldg(fb + (size_t)cq[j2]*L_), acc);
        float v = acc;

        const unsigned full = 0xffffffffu;
        float sx = v, sy = v*v;
        #pragma unroll
        for (int o = 16; o > 0; o >>= 1){
            sx += __shfl_xor_sync(full, sx, o);
            sy += __shfl_xor_sync(full, sy, o);
        }
        int lane = t & 31, wrp = t >> 5;
        if (lane == 0) sred[wrp] = make_float2(sx, sy);
        __syncthreads();
        if (t == 0){
            float mx = 0.f, my = 0.f;
            #pragma unroll
            for (int k = 0; k < 8; k++){ mx += sred[k].x; my += sred[k].y; }
            float mu  = mx * (1.0f/256.0f);
            float var = my * (1.0f/256.0f) - mu*mu;
            s_mu = mu;
            s_rstd = rsqrtf(var + 1e-5f);
        }
        __syncthreads();

        float o = (v - s_mu) * s_rstd * __ldg(&gamma[c]) + __ldg(&beta[c]);
        out[((size_t)c*THW_ + p)*L_ + l] = o;
    }
}

// ============================================================
extern "C" void kernel_launch(void* const* d_in, const int* in_sizes, int n_in,
                              void* d_out, int out_size)
{
    const float* feats = (const float*)d_in[0];
    const float* pos   = (const float*)d_in[1];
    const float* W1    = (const float*)d_in[2];
    const float* b1    = (const float*)d_in[3];
    const float* W2    = (const float*)d_in[4];
    const float* b2    = (const float*)d_in[5];
    const float* Wn    = (const float*)d_in[6];
    const float* bn    = (const float*)d_in[7];
    // d_in[8]=Wl, d_in[9]=bl dead (softmax row-sum == 1; LN scale-invariant)
    const float* Woff  = (const float*)d_in[10];
    const float* boff  = (const float*)d_in[11];
    const float* Ww    = (const float*)d_in[12];
    const float* bw    = (const float*)d_in[13];
    const float* gamma = (const float*)d_in[14];
    const float* beta  = (const float*)d_in[15];
    float* out = (float*)d_out;

    int write_next = (out_size >= FEAT_OUT_ELEMS + NROWS) ? 1 : 0;

    static int smem_set = 0;
    if (!smem_set){
        cudaFuncSetAttribute(fused_kernel, cudaFuncAttributeMaxDynamicSharedMemorySize,
                             FUSED_SMEM_BYTES);
        smem_set = 1;
    }

    fused_kernel<<<NB, 256, FUSED_SMEM_BYTES>>>(feats, pos, W1, b1, W2, b2, Wn, bn,
                                                Woff, boff, Ww, bw, gamma, beta,
                                                out, write_next);
}